// round 1
// baseline (speedup 1.0000x reference)
#include <cuda_runtime.h>
#include <math.h>

#define HIDDEN 2048
#define NH 16
#define HD 128
#define SEQ 2048
#define BATCH 2
#define MTOT (BATCH*SEQ)   /* 4096 */

// ---------------- scratch (static device memory; no allocation) ----------------
__device__ float g_q[(size_t)MTOT * HIDDEN];   // [B, nh, S, hd]
__device__ float g_k[(size_t)MTOT * HIDDEN];   // [B, nh, S, hd]
__device__ float g_v[(size_t)MTOT * HIDDEN];   // [B, nh, S, hd]
__device__ float g_a[(size_t)MTOT * HIDDEN];   // [B, S, H] (merged heads)

// =======================================================================
// GEMM (NT): C[m,n] = sum_k A[m,k] * W[n,k] + bias[n]
// A: [M,K] row-major, W: [N,K] row-major (torch [out,in] layout)
// remap=1: write C in [B, nh, S, hd] layout (for Q/K/V)
// remap=0: write C row-major [M,N]
// BM=BN=128, BK=16, 256 threads, 8x8 per-thread microtile
// =======================================================================
__global__ __launch_bounds__(256, 2)
void gemm_nt_bias(const float* __restrict__ A, const float* __restrict__ W,
                  const float* __restrict__ bias, float* __restrict__ C,
                  int M, int N, int K, int remap)
{
    __shared__ float As[16][132];   // [k][m], padded
    __shared__ float Bs[16][132];   // [k][n], padded

    const int tid = threadIdx.x;
    const int tx = tid & 15;        // 0..15 -> n direction
    const int ty = tid >> 4;        // 0..15 -> m direction
    const int m0 = blockIdx.y * 128;
    const int n0 = blockIdx.x * 128;

    float acc[8][8];
#pragma unroll
    for (int i = 0; i < 8; i++)
#pragma unroll
        for (int j = 0; j < 8; j++) acc[i][j] = 0.f;

    for (int k0 = 0; k0 < K; k0 += 16) {
        // load 128x16 tiles of A and W (as float4 along k), store transposed
#pragma unroll
        for (int l = 0; l < 2; l++) {
            int idx = tid + l * 256;          // 0..511
            int row = idx >> 2;               // 0..127
            int kc  = (idx & 3) << 2;         // 0,4,8,12
            float4 va = *(const float4*)(A + (size_t)(m0 + row) * K + k0 + kc);
            As[kc + 0][row] = va.x; As[kc + 1][row] = va.y;
            As[kc + 2][row] = va.z; As[kc + 3][row] = va.w;
            float4 vb = *(const float4*)(W + (size_t)(n0 + row) * K + k0 + kc);
            Bs[kc + 0][row] = vb.x; Bs[kc + 1][row] = vb.y;
            Bs[kc + 2][row] = vb.z; Bs[kc + 3][row] = vb.w;
        }
        __syncthreads();

#pragma unroll
        for (int k = 0; k < 16; k++) {
            float a[8], b[8];
            *(float4*)(a)     = *(const float4*)&As[k][ty * 8];
            *(float4*)(a + 4) = *(const float4*)&As[k][ty * 8 + 4];
            *(float4*)(b)     = *(const float4*)&Bs[k][tx * 8];
            *(float4*)(b + 4) = *(const float4*)&Bs[k][tx * 8 + 4];
#pragma unroll
            for (int i = 0; i < 8; i++)
#pragma unroll
                for (int j = 0; j < 8; j++)
                    acc[i][j] += a[i] * b[j];
        }
        __syncthreads();
    }

    // epilogue: bias + store
#pragma unroll
    for (int i = 0; i < 8; i++) {
        int mm = m0 + ty * 8 + i;
        if (!remap) {
            float* cp = C + (size_t)mm * N + n0 + tx * 8;
#pragma unroll
            for (int j = 0; j < 8; j++)
                cp[j] = acc[i][j] + bias[n0 + tx * 8 + j];
        } else {
            int b = mm >> 11;        // / SEQ
            int s = mm & 2047;       // % SEQ
#pragma unroll
            for (int j = 0; j < 8; j++) {
                int n = n0 + tx * 8 + j;
                int h = n >> 7;      // / HD
                int d = n & 127;     // % HD
                C[((size_t)((b << 4) + h) * SEQ + s) * HD + d] = acc[i][j] + bias[n];
            }
        }
    }
}

// =======================================================================
// Flash attention (causal, online softmax), fp32.
// grid: (S/64, B*nh), block: 256 threads (16x16 logical)
// Br = Bc = 64, hd = 128.
// Thread (tx,ty): scores s[4][4] rows ty*4+i cols tx*4+j;
//                 output  o[4][8] rows ty*4+i dims tx*8+dd.
// Out written in merged-heads [B, S, H] layout.
// =======================================================================
#define QT_S 68    // stride for Qt/Kt [d][row]
#define V_S 132    // stride for Vs   [j][d]
#define P_S 68     // stride for Ps   [r][j]
#define FLASH_SMEM ((128*QT_S*2 + 64*V_S + 64*P_S) * 4)

__global__ __launch_bounds__(256)
void flash_kernel(const float* __restrict__ Q, const float* __restrict__ K,
                  const float* __restrict__ V, float* __restrict__ Out, int S)
{
    extern __shared__ float sm[];
    float* Qt = sm;                    // [128][QT_S]  (d-major, transposed)
    float* Kt = Qt + 128 * QT_S;       // [128][QT_S]
    float* Vs = Kt + 128 * QT_S;       // [64][V_S]
    float* Ps = Vs + 64 * V_S;         // [64][P_S]

    const int tid = threadIdx.x;
    const int tx = tid & 15;
    const int ty = tid >> 4;
    const int qb = blockIdx.x;
    const int bh = blockIdx.y;         // b*NH + h
    const float scale = 0.08838834764831845f;   // 1/sqrt(128)

    const float* Qg = Q + ((size_t)bh * S + qb * 64) * HD;
    const float* Kg = K + (size_t)bh * S * HD;
    const float* Vg = V + (size_t)bh * S * HD;

    // load Q tile (64x128) transposed + pre-scaled
#pragma unroll
    for (int l = 0; l < 8; l++) {
        int idx = tid + l * 256;        // float4 index 0..2047
        int row = idx >> 5;             // 0..63
        int d   = (idx & 31) << 2;      // 0..124
        float4 v = *(const float4*)&Qg[row * HD + d];
        Qt[(d + 0) * QT_S + row] = v.x * scale;
        Qt[(d + 1) * QT_S + row] = v.y * scale;
        Qt[(d + 2) * QT_S + row] = v.z * scale;
        Qt[(d + 3) * QT_S + row] = v.w * scale;
    }

    float o[4][8];
    float mrow[4], lrow[4];
#pragma unroll
    for (int i = 0; i < 4; i++) {
        mrow[i] = -1e30f; lrow[i] = 0.f;
#pragma unroll
        for (int dd = 0; dd < 8; dd++) o[i][dd] = 0.f;
    }

    const int nkb = qb + 1;   // causal: only tiles on/below diagonal
    for (int kb = 0; kb < nkb; kb++) {
        __syncthreads();   // Kt/Vs/Ps free (prev PV done); Qt ready (1st iter)

        // load K tile transposed, V tile natural
#pragma unroll
        for (int l = 0; l < 8; l++) {
            int idx = tid + l * 256;
            int row = idx >> 5;
            int d   = (idx & 31) << 2;
            float4 kv = *(const float4*)&Kg[(kb * 64 + row) * HD + d];
            Kt[(d + 0) * QT_S + row] = kv.x;
            Kt[(d + 1) * QT_S + row] = kv.y;
            Kt[(d + 2) * QT_S + row] = kv.z;
            Kt[(d + 3) * QT_S + row] = kv.w;
            *(float4*)&Vs[row * V_S + d] = *(const float4*)&Vg[(kb * 64 + row) * HD + d];
        }
        __syncthreads();

        // scores: s[i][j] = q_row . k_col  (Q pre-scaled)
        float s[4][4];
#pragma unroll
        for (int i = 0; i < 4; i++)
#pragma unroll
            for (int j = 0; j < 4; j++) s[i][j] = 0.f;

#pragma unroll 4
        for (int d = 0; d < 128; d++) {
            float a[4], b[4];
            *(float4*)a = *(const float4*)&Qt[d * QT_S + ty * 4];
            *(float4*)b = *(const float4*)&Kt[d * QT_S + tx * 4];
#pragma unroll
            for (int i = 0; i < 4; i++)
#pragma unroll
                for (int j = 0; j < 4; j++)
                    s[i][j] += a[i] * b[j];
        }

        // causal mask on diagonal tile (qb*64 == kb*64 offsets cancel)
        if (kb == qb) {
#pragma unroll
            for (int i = 0; i < 4; i++)
#pragma unroll
                for (int j = 0; j < 4; j++)
                    if (tx * 4 + j > ty * 4 + i) s[i][j] = -1e30f;
        }

        // online softmax per row (rows owned by this thread: ty*4+i)
#pragma unroll
        for (int i = 0; i < 4; i++) {
            float mx = s[i][0];
#pragma unroll
            for (int j = 1; j < 4; j++) mx = fmaxf(mx, s[i][j]);
#pragma unroll
            for (int off = 8; off >= 1; off >>= 1)
                mx = fmaxf(mx, __shfl_xor_sync(0xffffffffu, mx, off));
            float mnew = fmaxf(mrow[i], mx);
            float alpha = __expf(mrow[i] - mnew);
            mrow[i] = mnew;
            float rs = 0.f;
#pragma unroll
            for (int j = 0; j < 4; j++) {
                s[i][j] = __expf(s[i][j] - mnew);
                rs += s[i][j];
            }
#pragma unroll
            for (int off = 8; off >= 1; off >>= 1)
                rs += __shfl_xor_sync(0xffffffffu, rs, off);
            lrow[i] = lrow[i] * alpha + rs;
#pragma unroll
            for (int dd = 0; dd < 8; dd++) o[i][dd] *= alpha;
            *(float4*)&Ps[(ty * 4 + i) * P_S + tx * 4] = *(float4*)&s[i][0];
        }
        __syncthreads();

        // O += P @ V
#pragma unroll 2
        for (int j = 0; j < 64; j++) {
            float p[4], v[8];
#pragma unroll
            for (int i = 0; i < 4; i++) p[i] = Ps[(ty * 4 + i) * P_S + j];
            *(float4*)(v)     = *(const float4*)&Vs[j * V_S + tx * 8];
            *(float4*)(v + 4) = *(const float4*)&Vs[j * V_S + tx * 8 + 4];
#pragma unroll
            for (int i = 0; i < 4; i++)
#pragma unroll
                for (int dd = 0; dd < 8; dd++)
                    o[i][dd] += p[i] * v[dd];
        }
    }

    // epilogue: normalize and store (merged-heads [B,S,H])
    const int b = bh >> 4;
    const int h = bh & 15;
#pragma unroll
    for (int i = 0; i < 4; i++) {
        float inv = 1.0f / lrow[i];
        int srow = qb * 64 + ty * 4 + i;
        float* op = Out + ((size_t)(b * S + srow)) * HIDDEN + h * HD + tx * 8;
        float4 r0, r1;
        r0.x = o[i][0] * inv; r0.y = o[i][1] * inv;
        r0.z = o[i][2] * inv; r0.w = o[i][3] * inv;
        r1.x = o[i][4] * inv; r1.y = o[i][5] * inv;
        r1.z = o[i][6] * inv; r1.w = o[i][7] * inv;
        *(float4*)(op)     = r0;
        *(float4*)(op + 4) = r1;
    }
}

// =======================================================================
extern "C" void kernel_launch(void* const* d_in, const int* in_sizes, int n_in,
                              void* d_out, int out_size)
{
    const float* x  = (const float*)d_in[0];
    const float* wq = (const float*)d_in[1];
    const float* bq = (const float*)d_in[2];
    const float* wk = (const float*)d_in[3];
    const float* bk = (const float*)d_in[4];
    const float* wv = (const float*)d_in[5];
    const float* bv = (const float*)d_in[6];
    const float* wo = (const float*)d_in[7];
    const float* bo = (const float*)d_in[8];
    float* out = (float*)d_out;

    float *q, *k, *v, *a;
    cudaGetSymbolAddress((void**)&q, g_q);
    cudaGetSymbolAddress((void**)&k, g_k);
    cudaGetSymbolAddress((void**)&v, g_v);
    cudaGetSymbolAddress((void**)&a, g_a);

    dim3 gg(HIDDEN / 128, MTOT / 128);

    // QKV projections (epilogue remaps to [B, nh, S, hd])
    gemm_nt_bias<<<gg, 256>>>(x, wq, bq, q, MTOT, HIDDEN, HIDDEN, 1);
    gemm_nt_bias<<<gg, 256>>>(x, wk, bk, k, MTOT, HIDDEN, HIDDEN, 1);
    gemm_nt_bias<<<gg, 256>>>(x, wv, bv, v, MTOT, HIDDEN, HIDDEN, 1);

    // causal flash attention -> merged-heads [B, S, H]
    cudaFuncSetAttribute(flash_kernel, cudaFuncAttributeMaxDynamicSharedMemorySize,
                         FLASH_SMEM);
    flash_kernel<<<dim3(SEQ / 64, BATCH * NH), 256, FLASH_SMEM>>>(q, k, v, a, SEQ);

    // output projection
    gemm_nt_bias<<<gg, 256>>>(a, wo, bo, out, MTOT, HIDDEN, HIDDEN, 0);
}

// round 3
// speedup vs baseline: 1.9880x; 1.9880x over previous
#include <cuda_runtime.h>
#include <math.h>
#include <stdint.h>

#define HIDDEN 2048
#define NH 16
#define HD 128
#define SEQ 2048
#define BATCH 2
#define MTOT (BATCH*SEQ)   /* 4096 */

// ---------------- scratch (static device memory; no allocation) ----------------
__device__ float g_q[(size_t)MTOT * HIDDEN];   // [B, nh, S, hd]
__device__ float g_k[(size_t)MTOT * HIDDEN];   // [B, nh, S, hd]
__device__ float g_v[(size_t)MTOT * HIDDEN];   // [B, nh, S, hd]
__device__ float g_a[(size_t)MTOT * HIDDEN];   // [B, S, H] (merged heads)

__device__ __forceinline__ uint32_t f2tf(float x) {
    uint32_t y;
    asm("cvt.rna.tf32.f32 %0, %1;" : "=r"(y) : "f"(x));
    return y;
}

#define LDSM4(R0,R1,R2,R3,ADDR) \
    asm volatile("ldmatrix.sync.aligned.m8n8.x4.shared.b16 {%0,%1,%2,%3}, [%4];" \
                 : "=r"(R0),"=r"(R1),"=r"(R2),"=r"(R3) : "r"(ADDR))

#define MMA_TF32(C0,C1,C2,C3,A0,A1,A2,A3,B0,B1) \
    asm volatile("mma.sync.aligned.m16n8k8.row.col.f32.tf32.tf32.f32 " \
                 "{%0,%1,%2,%3},{%4,%5,%6,%7},{%8,%9},{%0,%1,%2,%3};" \
                 : "+f"(C0),"+f"(C1),"+f"(C2),"+f"(C3) \
                 : "r"(A0),"r"(A1),"r"(A2),"r"(A3),"r"(B0),"r"(B1))

// =======================================================================
// tf32 tensor-core GEMM (NT): C[m,n] = sum_k A[m,k]*W[n,k] + bias[n]
// A: [M,K] row-major; W: [N,K] row-major (torch [out,in]).
// BM=BN=128, BK=32, 256 threads = 8 warps (2m x 4n), warptile 64x32.
// remap=1: scatter C into [B, nh, S, hd]; remap=0: row-major [M,N].
// =======================================================================
#define TILE_U32 (128*32)          /* one smem tile in uint32 */
#define GEMM_SMEM (4*TILE_U32*4)   /* A(2 bufs) + B(2 bufs), bytes = 65536 */

__global__ __launch_bounds__(256)
void gemm_tf32(const float* __restrict__ A, const float* __restrict__ W,
               const float* __restrict__ bias, float* __restrict__ C,
               int M, int N, int K, int remap)
{
    extern __shared__ uint32_t smem_u[];
    // layout: [bufA0][bufA1][bufB0][bufB1], each 16KB
    const int tid  = threadIdx.x;
    const int lane = tid & 31;
    const int wid  = tid >> 5;
    const int warp_m = wid >> 2;        // 0..1
    const int warp_n = wid & 3;         // 0..3
    const int m0 = blockIdx.y * 128;
    const int n0 = blockIdx.x * 128;

    // ldmatrix lane decode
    const int mat = lane >> 3, r = lane & 7;
    const int a_sh = mat >> 1, a_roff = r + ((mat & 1) << 3);
    const int b_sh = mat & 1,  b_roff = r + ((mat >> 1) << 3);

    // global load mapping (4 float4 per thread per operand)
    const int grow = tid >> 3;       // base row (adds 32 per l)
    const int gseg = tid & 7;        // 16B segment within 128B row

    const uint32_t sbase = (uint32_t)__cvta_generic_to_shared(smem_u);
    const uint32_t sA0 = sbase;
    const uint32_t sB0 = sbase + 2 * TILE_U32 * 4;

    // per-lane ldmatrix row-byte offsets
    uint32_t rowbA[4], rowbB[2];
#pragma unroll
    for (int mf = 0; mf < 4; mf++)
        rowbA[mf] = (uint32_t)(warp_m * 64 + mf * 16 + a_roff) * 128u;
#pragma unroll
    for (int pb = 0; pb < 2; pb++)
        rowbB[pb] = (uint32_t)(warp_n * 32 + pb * 16 + b_roff) * 128u;

    float acc[4][4][4];
#pragma unroll
    for (int i = 0; i < 4; i++)
#pragma unroll
        for (int j = 0; j < 4; j++)
#pragma unroll
            for (int c = 0; c < 4; c++) acc[i][j][c] = 0.f;

    const int KT = K >> 5;   // K/32
    float4 va[4], vb[4];

    // ---- prologue: load tile 0 ----
#pragma unroll
    for (int l = 0; l < 4; l++) {
        int row = grow + 32 * l;
        va[l] = *(const float4*)(A + (size_t)(m0 + row) * K + gseg * 4);
        vb[l] = *(const float4*)(W + (size_t)(n0 + row) * K + gseg * 4);
    }
#pragma unroll
    for (int l = 0; l < 4; l++) {
        int row = grow + 32 * l;
        int sseg = gseg ^ (row & 7);
        uint4 ua = make_uint4(f2tf(va[l].x), f2tf(va[l].y), f2tf(va[l].z), f2tf(va[l].w));
        uint4 ub = make_uint4(f2tf(vb[l].x), f2tf(vb[l].y), f2tf(vb[l].z), f2tf(vb[l].w));
        *(uint4*)(smem_u + row * 32 + sseg * 4) = ua;
        *(uint4*)(smem_u + 2 * TILE_U32 + row * 32 + sseg * 4) = ub;
    }
    __syncthreads();

    int buf = 0;
    for (int kt = 0; kt < KT; kt++) {
        // issue global loads for next tile
        if (kt + 1 < KT) {
            int k0 = (kt + 1) * 32;
#pragma unroll
            for (int l = 0; l < 4; l++) {
                int row = grow + 32 * l;
                va[l] = *(const float4*)(A + (size_t)(m0 + row) * K + k0 + gseg * 4);
                vb[l] = *(const float4*)(W + (size_t)(n0 + row) * K + k0 + gseg * 4);
            }
        }

        // compute on current buffer
        const uint32_t abase = sA0 + buf * (TILE_U32 * 4);
        const uint32_t bbase = sB0 + buf * (TILE_U32 * 4);
#pragma unroll
        for (int ks = 0; ks < 4; ks++) {
            uint32_t af[4][4];
            uint32_t bf[4][2];
#pragma unroll
            for (int mf = 0; mf < 4; mf++) {
                uint32_t addr = abase + rowbA[mf] + (uint32_t)((((ks << 1) + a_sh) ^ r) << 4);
                LDSM4(af[mf][0], af[mf][1], af[mf][2], af[mf][3], addr);
            }
#pragma unroll
            for (int pb = 0; pb < 2; pb++) {
                uint32_t addr = bbase + rowbB[pb] + (uint32_t)((((ks << 1) + b_sh) ^ r) << 4);
                uint32_t t0, t1, t2, t3;
                LDSM4(t0, t1, t2, t3, addr);
                bf[pb * 2 + 0][0] = t0; bf[pb * 2 + 0][1] = t1;   // n-block 2pb
                bf[pb * 2 + 1][0] = t2; bf[pb * 2 + 1][1] = t3;   // n-block 2pb+1
            }
#pragma unroll
            for (int mf = 0; mf < 4; mf++)
#pragma unroll
                for (int nf = 0; nf < 4; nf++)
                    MMA_TF32(acc[mf][nf][0], acc[mf][nf][1], acc[mf][nf][2], acc[mf][nf][3],
                             af[mf][0], af[mf][1], af[mf][2], af[mf][3],
                             bf[nf][0], bf[nf][1]);
        }

        // store next tile into the other buffer
        if (kt + 1 < KT) {
            uint32_t* dA = smem_u + (buf ^ 1) * TILE_U32;
            uint32_t* dB = smem_u + 2 * TILE_U32 + (buf ^ 1) * TILE_U32;
#pragma unroll
            for (int l = 0; l < 4; l++) {
                int row = grow + 32 * l;
                int sseg = gseg ^ (row & 7);
                uint4 ua = make_uint4(f2tf(va[l].x), f2tf(va[l].y), f2tf(va[l].z), f2tf(va[l].w));
                uint4 ub = make_uint4(f2tf(vb[l].x), f2tf(vb[l].y), f2tf(vb[l].z), f2tf(vb[l].w));
                *(uint4*)(dA + row * 32 + sseg * 4) = ua;
                *(uint4*)(dB + row * 32 + sseg * 4) = ub;
            }
        }
        __syncthreads();
        buf ^= 1;
    }

    // ---- epilogue: bias + store ----
    const int group = lane >> 2;      // row within 16-row frag
    const int tcol  = lane & 3;       // col pair
#pragma unroll
    for (int mf = 0; mf < 4; mf++) {
#pragma unroll
        for (int nf = 0; nf < 4; nf++) {
            int col = n0 + warp_n * 32 + nf * 8 + tcol * 2;
            float b0 = bias[col], b1 = bias[col + 1];
            int mrow0 = m0 + warp_m * 64 + mf * 16 + group;
#pragma unroll
            for (int half = 0; half < 2; half++) {
                int mrow = mrow0 + half * 8;
                float v0 = acc[mf][nf][half * 2 + 0] + b0;
                float v1 = acc[mf][nf][half * 2 + 1] + b1;
                if (!remap) {
                    float2* cp = (float2*)(C + (size_t)mrow * N + col);
                    *cp = make_float2(v0, v1);
                } else {
                    int b = mrow >> 11;
                    int s = mrow & 2047;
                    int h = col >> 7;
                    int d = col & 127;
                    float2* cp = (float2*)(C + (((size_t)((b << 4) + h) * SEQ + s) << 7) + d);
                    *cp = make_float2(v0, v1);
                }
            }
        }
    }
}

// =======================================================================
// Flash attention (causal, online softmax), fp32 — unchanged from R1.
// =======================================================================
#define QT_S 68
#define V_S 132
#define P_S 68
#define FLASH_SMEM ((128*QT_S*2 + 64*V_S + 64*P_S) * 4)

__global__ __launch_bounds__(256)
void flash_kernel(const float* __restrict__ Q, const float* __restrict__ K,
                  const float* __restrict__ V, float* __restrict__ Out, int S)
{
    extern __shared__ float sm[];
    float* Qt = sm;
    float* Kt = Qt + 128 * QT_S;
    float* Vs = Kt + 128 * QT_S;
    float* Ps = Vs + 64 * V_S;

    const int tid = threadIdx.x;
    const int tx = tid & 15;
    const int ty = tid >> 4;
    const int qb = blockIdx.x;
    const int bh = blockIdx.y;
    const float scale = 0.08838834764831845f;

    const float* Qg = Q + ((size_t)bh * S + qb * 64) * HD;
    const float* Kg = K + (size_t)bh * S * HD;
    const float* Vg = V + (size_t)bh * S * HD;

#pragma unroll
    for (int l = 0; l < 8; l++) {
        int idx = tid + l * 256;
        int row = idx >> 5;
        int d   = (idx & 31) << 2;
        float4 v = *(const float4*)&Qg[row * HD + d];
        Qt[(d + 0) * QT_S + row] = v.x * scale;
        Qt[(d + 1) * QT_S + row] = v.y * scale;
        Qt[(d + 2) * QT_S + row] = v.z * scale;
        Qt[(d + 3) * QT_S + row] = v.w * scale;
    }

    float o[4][8];
    float mrow[4], lrow[4];
#pragma unroll
    for (int i = 0; i < 4; i++) {
        mrow[i] = -1e30f; lrow[i] = 0.f;
#pragma unroll
        for (int dd = 0; dd < 8; dd++) o[i][dd] = 0.f;
    }

    const int nkb = qb + 1;
    for (int kb = 0; kb < nkb; kb++) {
        __syncthreads();
#pragma unroll
        for (int l = 0; l < 8; l++) {
            int idx = tid + l * 256;
            int row = idx >> 5;
            int d   = (idx & 31) << 2;
            float4 kv = *(const float4*)&Kg[(kb * 64 + row) * HD + d];
            Kt[(d + 0) * QT_S + row] = kv.x;
            Kt[(d + 1) * QT_S + row] = kv.y;
            Kt[(d + 2) * QT_S + row] = kv.z;
            Kt[(d + 3) * QT_S + row] = kv.w;
            *(float4*)&Vs[row * V_S + d] = *(const float4*)&Vg[(kb * 64 + row) * HD + d];
        }
        __syncthreads();

        float s[4][4];
#pragma unroll
        for (int i = 0; i < 4; i++)
#pragma unroll
            for (int j = 0; j < 4; j++) s[i][j] = 0.f;

#pragma unroll 4
        for (int d = 0; d < 128; d++) {
            float a[4], b[4];
            *(float4*)a = *(const float4*)&Qt[d * QT_S + ty * 4];
            *(float4*)b = *(const float4*)&Kt[d * QT_S + tx * 4];
#pragma unroll
            for (int i = 0; i < 4; i++)
#pragma unroll
                for (int j = 0; j < 4; j++)
                    s[i][j] += a[i] * b[j];
        }

        if (kb == qb) {
#pragma unroll
            for (int i = 0; i < 4; i++)
#pragma unroll
                for (int j = 0; j < 4; j++)
                    if (tx * 4 + j > ty * 4 + i) s[i][j] = -1e30f;
        }

#pragma unroll
        for (int i = 0; i < 4; i++) {
            float mx = s[i][0];
#pragma unroll
            for (int j = 1; j < 4; j++) mx = fmaxf(mx, s[i][j]);
#pragma unroll
            for (int off = 8; off >= 1; off >>= 1)
                mx = fmaxf(mx, __shfl_xor_sync(0xffffffffu, mx, off));
            float mnew = fmaxf(mrow[i], mx);
            float alpha = __expf(mrow[i] - mnew);
            mrow[i] = mnew;
            float rs = 0.f;
#pragma unroll
            for (int j = 0; j < 4; j++) {
                s[i][j] = __expf(s[i][j] - mnew);
                rs += s[i][j];
            }
#pragma unroll
            for (int off = 8; off >= 1; off >>= 1)
                rs += __shfl_xor_sync(0xffffffffu, rs, off);
            lrow[i] = lrow[i] * alpha + rs;
#pragma unroll
            for (int dd = 0; dd < 8; dd++) o[i][dd] *= alpha;
            *(float4*)&Ps[(ty * 4 + i) * P_S + tx * 4] = *(float4*)&s[i][0];
        }
        __syncthreads();

#pragma unroll 2
        for (int j = 0; j < 64; j++) {
            float p[4], v[8];
#pragma unroll
            for (int i = 0; i < 4; i++) p[i] = Ps[(ty * 4 + i) * P_S + j];
            *(float4*)(v)     = *(const float4*)&Vs[j * V_S + tx * 8];
            *(float4*)(v + 4) = *(const float4*)&Vs[j * V_S + tx * 8 + 4];
#pragma unroll
            for (int i = 0; i < 4; i++)
#pragma unroll
                for (int dd = 0; dd < 8; dd++)
                    o[i][dd] += p[i] * v[dd];
        }
    }

    const int b = bh >> 4;
    const int h = bh & 15;
#pragma unroll
    for (int i = 0; i < 4; i++) {
        float inv = 1.0f / lrow[i];
        int srow = qb * 64 + ty * 4 + i;
        float* op = Out + ((size_t)(b * S + srow)) * HIDDEN + h * HD + tx * 8;
        float4 r0, r1;
        r0.x = o[i][0] * inv; r0.y = o[i][1] * inv;
        r0.z = o[i][2] * inv; r0.w = o[i][3] * inv;
        r1.x = o[i][4] * inv; r1.y = o[i][5] * inv;
        r1.z = o[i][6] * inv; r1.w = o[i][7] * inv;
        *(float4*)(op)     = r0;
        *(float4*)(op + 4) = r1;
    }
}

// =======================================================================
extern "C" void kernel_launch(void* const* d_in, const int* in_sizes, int n_in,
                              void* d_out, int out_size)
{
    const float* x  = (const float*)d_in[0];
    const float* wq = (const float*)d_in[1];
    const float* bq = (const float*)d_in[2];
    const float* wk = (const float*)d_in[3];
    const float* bk = (const float*)d_in[4];
    const float* wv = (const float*)d_in[5];
    const float* bv = (const float*)d_in[6];
    const float* wo = (const float*)d_in[7];
    const float* bo = (const float*)d_in[8];
    float* out = (float*)d_out;

    float *q, *k, *v, *a;
    cudaGetSymbolAddress((void**)&q, g_q);
    cudaGetSymbolAddress((void**)&k, g_k);
    cudaGetSymbolAddress((void**)&v, g_v);
    cudaGetSymbolAddress((void**)&a, g_a);

    static int attr_done = 0;
    if (!attr_done) {
        cudaFuncSetAttribute(gemm_tf32, cudaFuncAttributeMaxDynamicSharedMemorySize, GEMM_SMEM);
        cudaFuncSetAttribute(flash_kernel, cudaFuncAttributeMaxDynamicSharedMemorySize, FLASH_SMEM);
        attr_done = 1;
    }

    dim3 gg(HIDDEN / 128, MTOT / 128);

    gemm_tf32<<<gg, 256, GEMM_SMEM>>>(x, wq, bq, q, MTOT, HIDDEN, HIDDEN, 1);
    gemm_tf32<<<gg, 256, GEMM_SMEM>>>(x, wk, bk, k, MTOT, HIDDEN, HIDDEN, 1);
    gemm_tf32<<<gg, 256, GEMM_SMEM>>>(x, wv, bv, v, MTOT, HIDDEN, HIDDEN, 1);

    flash_kernel<<<dim3(SEQ / 64, BATCH * NH), 256, FLASH_SMEM>>>(q, k, v, a, SEQ);

    gemm_tf32<<<gg, 256, GEMM_SMEM>>>(a, wo, bo, out, MTOT, HIDDEN, HIDDEN, 0);
}

// round 4
// speedup vs baseline: 3.4312x; 1.7259x over previous
#include <cuda_runtime.h>
#include <math.h>
#include <stdint.h>

#define HIDDEN 2048
#define NH 16
#define HD 128
#define SEQ 2048
#define BATCH 2
#define MTOT (BATCH*SEQ)   /* 4096 */

// ---------------- scratch (static device memory; no allocation) ----------------
__device__ float g_q [(size_t)MTOT * HIDDEN];   // [B, nh, S, hd]
__device__ float g_k [(size_t)MTOT * HIDDEN];   // [B, nh, S, hd]
__device__ float g_v [(size_t)MTOT * HIDDEN];   // [B, nh, S, hd]
__device__ float g_vt[(size_t)MTOT * HIDDEN];   // [B, nh, hd, S]  (V transposed)
__device__ float g_a [(size_t)MTOT * HIDDEN];   // [B, S, H] (merged heads)

__device__ __forceinline__ uint32_t f2tf(float x) {
    uint32_t y;
    asm("cvt.rna.tf32.f32 %0, %1;" : "=r"(y) : "f"(x));
    return y;
}

#define LDSM4(R0,R1,R2,R3,ADDR) \
    asm volatile("ldmatrix.sync.aligned.m8n8.x4.shared.b16 {%0,%1,%2,%3}, [%4];" \
                 : "=r"(R0),"=r"(R1),"=r"(R2),"=r"(R3) : "r"(ADDR))

#define MMA_TF32(C0,C1,C2,C3,A0,A1,A2,A3,B0,B1) \
    asm volatile("mma.sync.aligned.m16n8k8.row.col.f32.tf32.tf32.f32 " \
                 "{%0,%1,%2,%3},{%4,%5,%6,%7},{%8,%9},{%0,%1,%2,%3};" \
                 : "+f"(C0),"+f"(C1),"+f"(C2),"+f"(C3) \
                 : "r"(A0),"r"(A1),"r"(A2),"r"(A3),"r"(B0),"r"(B1))

// =======================================================================
// tf32 tensor-core GEMM (NT) — unchanged from R2/R3.
// =======================================================================
#define TILE_U32 (128*32)
#define GEMM_SMEM (4*TILE_U32*4)

__global__ __launch_bounds__(256)
void gemm_tf32(const float* __restrict__ A, const float* __restrict__ W,
               const float* __restrict__ bias, float* __restrict__ C,
               int M, int N, int K, int remap)
{
    extern __shared__ uint32_t smem_u[];
    const int tid  = threadIdx.x;
    const int lane = tid & 31;
    const int wid  = tid >> 5;
    const int warp_m = wid >> 2;
    const int warp_n = wid & 3;
    const int m0 = blockIdx.y * 128;
    const int n0 = blockIdx.x * 128;

    const int mat = lane >> 3, r = lane & 7;
    const int a_sh = mat >> 1, a_roff = r + ((mat & 1) << 3);
    const int b_sh = mat & 1,  b_roff = r + ((mat >> 1) << 3);

    const int grow = tid >> 3;
    const int gseg = tid & 7;

    const uint32_t sbase = (uint32_t)__cvta_generic_to_shared(smem_u);
    const uint32_t sA0 = sbase;
    const uint32_t sB0 = sbase + 2 * TILE_U32 * 4;

    uint32_t rowbA[4], rowbB[2];
#pragma unroll
    for (int mf = 0; mf < 4; mf++)
        rowbA[mf] = (uint32_t)(warp_m * 64 + mf * 16 + a_roff) * 128u;
#pragma unroll
    for (int pb = 0; pb < 2; pb++)
        rowbB[pb] = (uint32_t)(warp_n * 32 + pb * 16 + b_roff) * 128u;

    float acc[4][4][4];
#pragma unroll
    for (int i = 0; i < 4; i++)
#pragma unroll
        for (int j = 0; j < 4; j++)
#pragma unroll
            for (int c = 0; c < 4; c++) acc[i][j][c] = 0.f;

    const int KT = K >> 5;
    float4 va[4], vb[4];

#pragma unroll
    for (int l = 0; l < 4; l++) {
        int row = grow + 32 * l;
        va[l] = *(const float4*)(A + (size_t)(m0 + row) * K + gseg * 4);
        vb[l] = *(const float4*)(W + (size_t)(n0 + row) * K + gseg * 4);
    }
#pragma unroll
    for (int l = 0; l < 4; l++) {
        int row = grow + 32 * l;
        int sseg = gseg ^ (row & 7);
        uint4 ua = make_uint4(f2tf(va[l].x), f2tf(va[l].y), f2tf(va[l].z), f2tf(va[l].w));
        uint4 ub = make_uint4(f2tf(vb[l].x), f2tf(vb[l].y), f2tf(vb[l].z), f2tf(vb[l].w));
        *(uint4*)(smem_u + row * 32 + sseg * 4) = ua;
        *(uint4*)(smem_u + 2 * TILE_U32 + row * 32 + sseg * 4) = ub;
    }
    __syncthreads();

    int buf = 0;
    for (int kt = 0; kt < KT; kt++) {
        if (kt + 1 < KT) {
            int k0 = (kt + 1) * 32;
#pragma unroll
            for (int l = 0; l < 4; l++) {
                int row = grow + 32 * l;
                va[l] = *(const float4*)(A + (size_t)(m0 + row) * K + k0 + gseg * 4);
                vb[l] = *(const float4*)(W + (size_t)(n0 + row) * K + k0 + gseg * 4);
            }
        }

        const uint32_t abase = sA0 + buf * (TILE_U32 * 4);
        const uint32_t bbase = sB0 + buf * (TILE_U32 * 4);
#pragma unroll
        for (int ks = 0; ks < 4; ks++) {
            uint32_t af[4][4];
            uint32_t bf[4][2];
#pragma unroll
            for (int mf = 0; mf < 4; mf++) {
                uint32_t addr = abase + rowbA[mf] + (uint32_t)((((ks << 1) + a_sh) ^ r) << 4);
                LDSM4(af[mf][0], af[mf][1], af[mf][2], af[mf][3], addr);
            }
#pragma unroll
            for (int pb = 0; pb < 2; pb++) {
                uint32_t addr = bbase + rowbB[pb] + (uint32_t)((((ks << 1) + b_sh) ^ r) << 4);
                uint32_t t0, t1, t2, t3;
                LDSM4(t0, t1, t2, t3, addr);
                bf[pb * 2 + 0][0] = t0; bf[pb * 2 + 0][1] = t1;
                bf[pb * 2 + 1][0] = t2; bf[pb * 2 + 1][1] = t3;
            }
#pragma unroll
            for (int mf = 0; mf < 4; mf++)
#pragma unroll
                for (int nf = 0; nf < 4; nf++)
                    MMA_TF32(acc[mf][nf][0], acc[mf][nf][1], acc[mf][nf][2], acc[mf][nf][3],
                             af[mf][0], af[mf][1], af[mf][2], af[mf][3],
                             bf[nf][0], bf[nf][1]);
        }

        if (kt + 1 < KT) {
            uint32_t* dA = smem_u + (buf ^ 1) * TILE_U32;
            uint32_t* dB = smem_u + 2 * TILE_U32 + (buf ^ 1) * TILE_U32;
#pragma unroll
            for (int l = 0; l < 4; l++) {
                int row = grow + 32 * l;
                int sseg = gseg ^ (row & 7);
                uint4 ua = make_uint4(f2tf(va[l].x), f2tf(va[l].y), f2tf(va[l].z), f2tf(va[l].w));
                uint4 ub = make_uint4(f2tf(vb[l].x), f2tf(vb[l].y), f2tf(vb[l].z), f2tf(vb[l].w));
                *(uint4*)(dA + row * 32 + sseg * 4) = ua;
                *(uint4*)(dB + row * 32 + sseg * 4) = ub;
            }
        }
        __syncthreads();
        buf ^= 1;
    }

    const int group = lane >> 2;
    const int tcol  = lane & 3;
#pragma unroll
    for (int mf = 0; mf < 4; mf++) {
#pragma unroll
        for (int nf = 0; nf < 4; nf++) {
            int col = n0 + warp_n * 32 + nf * 8 + tcol * 2;
            float b0 = bias[col], b1 = bias[col + 1];
            int mrow0 = m0 + warp_m * 64 + mf * 16 + group;
#pragma unroll
            for (int half = 0; half < 2; half++) {
                int mrow = mrow0 + half * 8;
                float v0 = acc[mf][nf][half * 2 + 0] + b0;
                float v1 = acc[mf][nf][half * 2 + 1] + b1;
                if (!remap) {
                    float2* cp = (float2*)(C + (size_t)mrow * N + col);
                    *cp = make_float2(v0, v1);
                } else {
                    int b = mrow >> 11;
                    int s = mrow & 2047;
                    int h = col >> 7;
                    int d = col & 127;
                    float2* cp = (float2*)(C + (((size_t)((b << 4) + h) * SEQ + s) << 7) + d);
                    *cp = make_float2(v0, v1);
                }
            }
        }
    }
}

// =======================================================================
// V transpose: [bh][s][d] -> [bh][d][s]   (per bh slice 2048x128 -> 128x2048)
// =======================================================================
__global__ __launch_bounds__(256)
void transpose_v(const float* __restrict__ in, float* __restrict__ out)
{
    __shared__ float t[32][33];
    const int bh = blockIdx.z;
    const int d0 = blockIdx.x * 32;
    const int s0 = blockIdx.y * 32;
    const float* ip = in  + (size_t)bh * SEQ * HD;
    float*       op = out + (size_t)bh * HD * SEQ;
    const int tx = threadIdx.x & 31;
    const int ty = threadIdx.x >> 5;   // 0..7
#pragma unroll
    for (int j = 0; j < 32; j += 8)
        t[ty + j][tx] = ip[(size_t)(s0 + ty + j) * HD + d0 + tx];
    __syncthreads();
#pragma unroll
    for (int j = 0; j < 32; j += 8)
        op[(size_t)(d0 + ty + j) * SEQ + s0 + tx] = t[tx][ty + j];
}

// =======================================================================
// tf32 flash attention (causal, online softmax).
// grid (S/64 reversed, B*nh), 256 threads = 8 warps: 4 row-groups x 2 col-groups.
// Br=Bc=64, hd=128. Smem: Qs[64x128] Ks[64x128] Vt[128x64] Ps[64x64] red[64].
// =======================================================================
#define FQ   0
#define FK   8192
#define FV   16384
#define FP   24576
#define FRED 28672
#define FLASH_SMEM ((28672 + 256) * 4)   /* 115712 B */

__global__ __launch_bounds__(256)
void flash_tf32(const float* __restrict__ Q, const float* __restrict__ K,
                const float* __restrict__ Vt, float* __restrict__ Out)
{
    extern __shared__ uint32_t sm[];
    float2* redp = (float2*)(sm + FRED);

    const int tid  = threadIdx.x;
    const int lane = tid & 31;
    const int wid  = tid >> 5;
    const int warp_m = wid & 3;          // 4 row groups of 16
    const int warp_n = wid >> 2;         // 2 col groups
    const int qb = (gridDim.x - 1) - blockIdx.x;   // heavy tiles first
    const int bh = blockIdx.y;
    const int g    = lane >> 2;
    const int tcol = lane & 3;
    const float scale = 0.08838834764831845f;   // 1/sqrt(128)

    const float* Qg = Q  + ((size_t)bh * SEQ + qb * 64) * HD;
    const float* Kg = K  + (size_t)bh * SEQ * HD;
    const float* Vg = Vt + (size_t)bh * HD * SEQ;

    const uint32_t sbase = (uint32_t)__cvta_generic_to_shared(sm);
    const int mat = lane >> 3, r = lane & 7;
    const int a_sh = mat >> 1, a_roff = r + ((mat & 1) << 3);
    const int b_sh = mat & 1,  b_roff = r + ((mat >> 1) << 3);

    // ldmatrix row base addresses (bytes)
    const uint32_t qa_base = sbase + FQ * 4 + (uint32_t)(warp_m * 16 + a_roff) * 512u;
    uint32_t kb_row[2];
#pragma unroll
    for (int pb = 0; pb < 2; pb++)
        kb_row[pb] = sbase + FK * 4 + (uint32_t)(warp_n * 32 + pb * 16 + b_roff) * 512u;
    const uint32_t pa_base = sbase + FP * 4 + (uint32_t)(warp_m * 16 + a_roff) * 256u;
    uint32_t vb_row[4];
#pragma unroll
    for (int pb = 0; pb < 4; pb++)
        vb_row[pb] = sbase + FV * 4 + (uint32_t)(warp_n * 64 + pb * 16 + b_roff) * 256u;

    // ---- load Q tile (tf32, pre-scaled, swizzled; 512B rows) ----
#pragma unroll
    for (int l = 0; l < 8; l++) {
        int idx = tid + l * 256;
        int row = idx >> 5;
        int seg = idx & 31;
        float4 v = *(const float4*)&Qg[row * HD + seg * 4];
        uint4 u = make_uint4(f2tf(v.x * scale), f2tf(v.y * scale),
                             f2tf(v.z * scale), f2tf(v.w * scale));
        *(uint4*)(sm + FQ + row * 128 + (seg ^ (row & 7)) * 4) = u;
    }

    float o[8][4];
#pragma unroll
    for (int nf = 0; nf < 8; nf++)
#pragma unroll
        for (int c = 0; c < 4; c++) o[nf][c] = 0.f;
    float mrow[2] = {-1e30f, -1e30f};
    float lrow[2] = {0.f, 0.f};

    const int nkb = qb + 1;
    for (int kb = 0; kb < nkb; kb++) {
        __syncthreads();   // prev PV done; Ks/Vt free (Qs ready first iter)

        // K tile (row-major [j][d], 512B rows)
#pragma unroll
        for (int l = 0; l < 8; l++) {
            int idx = tid + l * 256;
            int row = idx >> 5;
            int seg = idx & 31;
            float4 v = *(const float4*)&Kg[(size_t)(kb * 64 + row) * HD + seg * 4];
            uint4 u = make_uint4(f2tf(v.x), f2tf(v.y), f2tf(v.z), f2tf(v.w));
            *(uint4*)(sm + FK + row * 128 + (seg ^ (row & 7)) * 4) = u;
        }
        // V^T tile (row-major [d][j], 256B rows) — coalesced from g_vt
#pragma unroll
        for (int l = 0; l < 8; l++) {
            int idx = tid + l * 256;
            int d   = idx >> 4;
            int seg = idx & 15;
            float4 v = *(const float4*)&Vg[(size_t)d * SEQ + kb * 64 + seg * 4];
            uint4 u = make_uint4(f2tf(v.x), f2tf(v.y), f2tf(v.z), f2tf(v.w));
            *(uint4*)(sm + FV + d * 64 + (seg ^ (d & 7)) * 4) = u;
        }
        __syncthreads();

        // ---- scores: S = Q . K^T  (64x64x128) ----
        float s[4][4];
#pragma unroll
        for (int nf = 0; nf < 4; nf++)
#pragma unroll
            for (int c = 0; c < 4; c++) s[nf][c] = 0.f;

#pragma unroll
        for (int ks = 0; ks < 16; ks++) {
            uint32_t a0, a1, a2, a3;
            LDSM4(a0, a1, a2, a3, qa_base + (uint32_t)((((ks << 1) + a_sh) ^ r) << 4));
            uint32_t bf[4][2];
#pragma unroll
            for (int pb = 0; pb < 2; pb++) {
                uint32_t t0, t1, t2, t3;
                LDSM4(t0, t1, t2, t3, kb_row[pb] + (uint32_t)((((ks << 1) + b_sh) ^ r) << 4));
                bf[pb * 2 + 0][0] = t0; bf[pb * 2 + 0][1] = t1;
                bf[pb * 2 + 1][0] = t2; bf[pb * 2 + 1][1] = t3;
            }
#pragma unroll
            for (int nf = 0; nf < 4; nf++)
                MMA_TF32(s[nf][0], s[nf][1], s[nf][2], s[nf][3],
                         a0, a1, a2, a3, bf[nf][0], bf[nf][1]);
        }

        // ---- causal mask on diagonal tile ----
        if (kb == qb) {
#pragma unroll
            for (int nf = 0; nf < 4; nf++)
#pragma unroll
                for (int c = 0; c < 4; c++) {
                    int lr = warp_m * 16 + g + (c >> 1) * 8;
                    int lc = warp_n * 32 + nf * 8 + 2 * tcol + (c & 1);
                    if (lc > lr) s[nf][c] = -1e30f;
                }
        }

        // ---- softmax (single cross-warp exchange) ----
        float p[2][8], mxw[2];
#pragma unroll
        for (int h = 0; h < 2; h++) {
            float mx = s[0][h * 2];
#pragma unroll
            for (int nf = 0; nf < 4; nf++) {
                mx = fmaxf(mx, s[nf][h * 2 + 0]);
                mx = fmaxf(mx, s[nf][h * 2 + 1]);
            }
            mx = fmaxf(mx, __shfl_xor_sync(0xffffffffu, mx, 1));
            mx = fmaxf(mx, __shfl_xor_sync(0xffffffffu, mx, 2));
            float sum = 0.f;
#pragma unroll
            for (int nf = 0; nf < 4; nf++) {
                float p0 = __expf(s[nf][h * 2 + 0] - mx);
                float p1 = __expf(s[nf][h * 2 + 1] - mx);
                p[h][nf * 2 + 0] = p0;
                p[h][nf * 2 + 1] = p1;
                sum += p0 + p1;
            }
            sum += __shfl_xor_sync(0xffffffffu, sum, 1);
            sum += __shfl_xor_sync(0xffffffffu, sum, 2);
            mxw[h] = mx;
            if (tcol == 0)
                redp[(warp_m * 16 + g + h * 8) * 2 + warp_n] = make_float2(mx, sum);
        }
        __syncthreads();

#pragma unroll
        for (int h = 0; h < 2; h++) {
            int row = warp_m * 16 + g + h * 8;
            float2 e0 = redp[row * 2 + 0];
            float2 e1 = redp[row * 2 + 1];
            float mnew  = fmaxf(mrow[h], fmaxf(e0.x, e1.x));
            float alpha = __expf(mrow[h] - mnew);
            lrow[h] = lrow[h] * alpha + e0.y * __expf(e0.x - mnew)
                                      + e1.y * __expf(e1.x - mnew);
            mrow[h] = mnew;
            float fac = __expf(mxw[h] - mnew);
            // store P (tf32) into Ps with swizzle
#pragma unroll
            for (int nf = 0; nf < 4; nf++) {
                int col = warp_n * 32 + nf * 8 + 2 * tcol;
                uint32_t w = FP + row * 64 + ((col >> 2) ^ (row & 7)) * 4 + (col & 3);
                uint2 u = make_uint2(f2tf(p[h][nf * 2 + 0] * fac),
                                     f2tf(p[h][nf * 2 + 1] * fac));
                *(uint2*)(sm + w) = u;
            }
            // rescale existing O
#pragma unroll
            for (int nfo = 0; nfo < 8; nfo++) {
                o[nfo][h * 2 + 0] *= alpha;
                o[nfo][h * 2 + 1] *= alpha;
            }
        }
        __syncthreads();   // Ps visible to all warps

        // ---- PV: O += P . V   (64x128x64) ----
#pragma unroll
        for (int ks = 0; ks < 8; ks++) {
            uint32_t a0, a1, a2, a3;
            LDSM4(a0, a1, a2, a3, pa_base + (uint32_t)((((ks << 1) + a_sh) ^ r) << 4));
            uint32_t bf[8][2];
#pragma unroll
            for (int pb = 0; pb < 4; pb++) {
                uint32_t t0, t1, t2, t3;
                LDSM4(t0, t1, t2, t3, vb_row[pb] + (uint32_t)((((ks << 1) + b_sh) ^ r) << 4));
                bf[pb * 2 + 0][0] = t0; bf[pb * 2 + 0][1] = t1;
                bf[pb * 2 + 1][0] = t2; bf[pb * 2 + 1][1] = t3;
            }
#pragma unroll
            for (int nf = 0; nf < 8; nf++)
                MMA_TF32(o[nf][0], o[nf][1], o[nf][2], o[nf][3],
                         a0, a1, a2, a3, bf[nf][0], bf[nf][1]);
        }
    }

    // ---- epilogue: normalize, store merged-heads [B,S,H] ----
    const int b = bh >> 4;
    const int hh = bh & 15;
#pragma unroll
    for (int h = 0; h < 2; h++) {
        float inv = 1.0f / lrow[h];
        int srow = qb * 64 + warp_m * 16 + g + h * 8;
        float* op = Out + ((size_t)(b * SEQ + srow)) * HIDDEN + hh * HD;
#pragma unroll
        for (int nf = 0; nf < 8; nf++) {
            int d = warp_n * 64 + nf * 8 + 2 * tcol;
            *(float2*)(op + d) = make_float2(o[nf][h * 2 + 0] * inv,
                                             o[nf][h * 2 + 1] * inv);
        }
    }
}

// =======================================================================
extern "C" void kernel_launch(void* const* d_in, const int* in_sizes, int n_in,
                              void* d_out, int out_size)
{
    const float* x  = (const float*)d_in[0];
    const float* wq = (const float*)d_in[1];
    const float* bq = (const float*)d_in[2];
    const float* wk = (const float*)d_in[3];
    const float* bk = (const float*)d_in[4];
    const float* wv = (const float*)d_in[5];
    const float* bv = (const float*)d_in[6];
    const float* wo = (const float*)d_in[7];
    const float* bo = (const float*)d_in[8];
    float* out = (float*)d_out;

    float *q, *k, *v, *vt, *a;
    cudaGetSymbolAddress((void**)&q,  g_q);
    cudaGetSymbolAddress((void**)&k,  g_k);
    cudaGetSymbolAddress((void**)&v,  g_v);
    cudaGetSymbolAddress((void**)&vt, g_vt);
    cudaGetSymbolAddress((void**)&a,  g_a);

    static int attr_done = 0;
    if (!attr_done) {
        cudaFuncSetAttribute(gemm_tf32, cudaFuncAttributeMaxDynamicSharedMemorySize, GEMM_SMEM);
        cudaFuncSetAttribute(flash_tf32, cudaFuncAttributeMaxDynamicSharedMemorySize, FLASH_SMEM);
        attr_done = 1;
    }

    dim3 gg(HIDDEN / 128, MTOT / 128);

    gemm_tf32<<<gg, 256, GEMM_SMEM>>>(x, wq, bq, q, MTOT, HIDDEN, HIDDEN, 1);
    gemm_tf32<<<gg, 256, GEMM_SMEM>>>(x, wk, bk, k, MTOT, HIDDEN, HIDDEN, 1);
    gemm_tf32<<<gg, 256, GEMM_SMEM>>>(x, wv, bv, v, MTOT, HIDDEN, HIDDEN, 1);

    transpose_v<<<dim3(HD / 32, SEQ / 32, BATCH * NH), 256>>>(v, vt);

    flash_tf32<<<dim3(SEQ / 64, BATCH * NH), 256, FLASH_SMEM>>>(q, k, vt, a);

    gemm_tf32<<<gg, 256, GEMM_SMEM>>>(a, wo, bo, out, MTOT, HIDDEN, HIDDEN, 0);
}

// round 6
// speedup vs baseline: 4.5894x; 1.3376x over previous
#include <cuda_runtime.h>
#include <math.h>
#include <stdint.h>

#define HIDDEN 2048
#define NH 16
#define HD 128
#define SEQ 2048
#define BATCH 2
#define MTOT (BATCH*SEQ)   /* 4096 */

// ---------------- scratch (static device memory; no allocation) ----------------
__device__ float g_xt [(size_t)MTOT * HIDDEN];        // x, tf32-rounded
__device__ float g_tw [(size_t)3 * HIDDEN * HIDDEN];  // wq|wk|wv packed, tf32-rounded
__device__ float g_two[(size_t)HIDDEN * HIDDEN];      // wo, tf32-rounded
__device__ float g_q  [(size_t)MTOT * HIDDEN];        // [B,nh,S,hd] (tf32 bits)
__device__ float g_k  [(size_t)MTOT * HIDDEN];        // [B,nh,S,hd] (tf32 bits)
__device__ float g_v  [(size_t)MTOT * HIDDEN];        // [B,nh,S,hd] (tf32 bits)
__device__ float g_vt [(size_t)MTOT * HIDDEN];        // [B,nh,hd,S] (tf32 bits)
__device__ float g_a  [(size_t)MTOT * HIDDEN];        // [B,S,H] attn out (tf32 bits)

__device__ __forceinline__ uint32_t f2tf(float x) {
    uint32_t y;
    asm("cvt.rna.tf32.f32 %0, %1;" : "=r"(y) : "f"(x));
    return y;
}

#define LDSM4(R0,R1,R2,R3,ADDR) \
    asm volatile("ldmatrix.sync.aligned.m8n8.x4.shared.b16 {%0,%1,%2,%3}, [%4];" \
                 : "=r"(R0),"=r"(R1),"=r"(R2),"=r"(R3) : "r"(ADDR))

#define MMA_TF32(C0,C1,C2,C3,A0,A1,A2,A3,B0,B1) \
    asm volatile("mma.sync.aligned.m16n8k8.row.col.f32.tf32.tf32.f32 " \
                 "{%0,%1,%2,%3},{%4,%5,%6,%7},{%8,%9},{%0,%1,%2,%3};" \
                 : "+f"(C0),"+f"(C1),"+f"(C2),"+f"(C3) \
                 : "r"(A0),"r"(A1),"r"(A2),"r"(A3),"r"(B0),"r"(B1))

#define CP_ASYNC16(SA, GA) \
    asm volatile("cp.async.cg.shared.global [%0], [%1], 16;" :: "r"(SA), "l"(GA))
#define CP_COMMIT() asm volatile("cp.async.commit_group;")
#define CP_WAIT1()  asm volatile("cp.async.wait_group 1;")

// =======================================================================
// tf32 round pre-pass (vectorized, grid-stride)
// =======================================================================
__global__ __launch_bounds__(256)
void cvt_tf32(float* __restrict__ dst, const float* __restrict__ src, int n4)
{
    int i = blockIdx.x * blockDim.x + threadIdx.x;
    int stride = gridDim.x * blockDim.x;
    for (; i < n4; i += stride) {
        float4 v = ((const float4*)src)[i];
        uint4 u = make_uint4(f2tf(v.x), f2tf(v.y), f2tf(v.z), f2tf(v.w));
        ((uint4*)dst)[i] = u;
    }
}

// =======================================================================
// cp.async 3-stage tf32 GEMM (NT): C[m,n] = sum_k A[m,k]*W[n,k] + bias
// A: [M,K] tf32 bits, W: [Nrows,K] tf32 bits (packed rows).
// mode 1 (QKV fused, N=6144): scatter rounded values into C0/C1/C2
//        = q/k/v [B,nh,S,hd]; bias selected from b0/b1/b2 by col>>11.
// mode 0: C0 row-major [M,N], bias b0, full fp32 output.
// BM=BN=128, BK=32, 256 threads = 8 warps (2m x 4n).
// =======================================================================
#define STAGES 3
#define STG_U32 8192                      /* A 4096 + B 4096 u32 per stage */
#define GEMM_SMEM (STAGES*STG_U32*4)      /* 98304 B */

__global__ __launch_bounds__(256)
void gemm_cp(const float* __restrict__ A, const float* __restrict__ W,
             const float* __restrict__ b0, const float* __restrict__ b1,
             const float* __restrict__ b2,
             float* __restrict__ C0, float* __restrict__ C1, float* __restrict__ C2,
             int M, int N, int K, int mode)
{
    extern __shared__ uint32_t smem_u[];
    const int tid  = threadIdx.x;
    const int lane = tid & 31;
    const int wid  = tid >> 5;
    const int warp_m = wid >> 2;
    const int warp_n = wid & 3;
    const int m0 = blockIdx.y * 128;
    const int n0 = blockIdx.x * 128;

    const int mat = lane >> 3, r = lane & 7;
    const int a_sh = mat >> 1, a_roff = r + ((mat & 1) << 3);
    const int b_sh = mat & 1,  b_roff = r + ((mat >> 1) << 3);

    const int grow = tid >> 3;       // 0..31, +32*l
    const int gseg = tid & 7;
    const int sseg = gseg ^ (grow & 7);   // row&7 == grow&7 for all l

    const uint32_t sbase = (uint32_t)__cvta_generic_to_shared(smem_u);

    // smem byte addresses for this thread's cp.async destinations (per stage add 32768)
    uint32_t sa[4], sb[4];
#pragma unroll
    for (int l = 0; l < 4; l++) {
        sa[l] = sbase + (uint32_t)((grow + 32 * l) * 32 + sseg * 4) * 4u;
        sb[l] = sa[l] + 16384u;
    }

    uint32_t rowbA[4], rowbB[2];
#pragma unroll
    for (int mf = 0; mf < 4; mf++)
        rowbA[mf] = (uint32_t)(warp_m * 64 + mf * 16 + a_roff) * 128u;
#pragma unroll
    for (int pb = 0; pb < 2; pb++)
        rowbB[pb] = (uint32_t)(warp_n * 32 + pb * 16 + b_roff) * 128u + 16384u;

    float acc[4][4][4];
#pragma unroll
    for (int i = 0; i < 4; i++)
#pragma unroll
        for (int j = 0; j < 4; j++)
#pragma unroll
            for (int c = 0; c < 4; c++) acc[i][j][c] = 0.f;

    const int KT = K >> 5;

    // ---- prologue: prefetch STAGES-1 tiles ----
#pragma unroll
    for (int s = 0; s < STAGES - 1; s++) {
        int k0 = s * 32;
        uint32_t soff = (uint32_t)s * 32768u;
#pragma unroll
        for (int l = 0; l < 4; l++) {
            int row = grow + 32 * l;
            CP_ASYNC16(sa[l] + soff, (const void*)(A + (size_t)(m0 + row) * K + k0 + gseg * 4));
            CP_ASYNC16(sb[l] + soff, (const void*)(W + (size_t)(n0 + row) * K + k0 + gseg * 4));
        }
        CP_COMMIT();
    }

    int stage = 0;
    for (int kt = 0; kt < KT; kt++) {
        CP_WAIT1();
        __syncthreads();

        const uint32_t abase = sbase + (uint32_t)stage * 32768u;
#pragma unroll
        for (int ks = 0; ks < 4; ks++) {
            uint32_t af[4][4];
            uint32_t bf[4][2];
#pragma unroll
            for (int mf = 0; mf < 4; mf++) {
                uint32_t addr = abase + rowbA[mf] + (uint32_t)((((ks << 1) + a_sh) ^ r) << 4);
                LDSM4(af[mf][0], af[mf][1], af[mf][2], af[mf][3], addr);
            }
#pragma unroll
            for (int pb = 0; pb < 2; pb++) {
                uint32_t addr = abase + rowbB[pb] + (uint32_t)((((ks << 1) + b_sh) ^ r) << 4);
                uint32_t t0, t1, t2, t3;
                LDSM4(t0, t1, t2, t3, addr);
                bf[pb * 2 + 0][0] = t0; bf[pb * 2 + 0][1] = t1;
                bf[pb * 2 + 1][0] = t2; bf[pb * 2 + 1][1] = t3;
            }
#pragma unroll
            for (int mf = 0; mf < 4; mf++)
#pragma unroll
                for (int nf = 0; nf < 4; nf++)
                    MMA_TF32(acc[mf][nf][0], acc[mf][nf][1], acc[mf][nf][2], acc[mf][nf][3],
                             af[mf][0], af[mf][1], af[mf][2], af[mf][3],
                             bf[nf][0], bf[nf][1]);
        }

        // prefetch tile kt+STAGES-1 into the stage just freed last iteration
        int kn = kt + STAGES - 1;
        if (kn < KT) {
            int k0 = kn * 32;
            uint32_t soff = (uint32_t)(kn % STAGES) * 32768u;
#pragma unroll
            for (int l = 0; l < 4; l++) {
                int row = grow + 32 * l;
                CP_ASYNC16(sa[l] + soff, (const void*)(A + (size_t)(m0 + row) * K + k0 + gseg * 4));
                CP_ASYNC16(sb[l] + soff, (const void*)(W + (size_t)(n0 + row) * K + k0 + gseg * 4));
            }
        }
        CP_COMMIT();
        stage = (stage + 1 == STAGES) ? 0 : stage + 1;
    }

    // ---- epilogue ----
    const int group = lane >> 2;
    const int tcol  = lane & 3;
    const int which = n0 >> 11;   // constant per block (128-wide tiles never cross)
    const float* bp = (which == 0) ? b0 : (which == 1) ? b1 : b2;
    float* Cw = (which == 0) ? C0 : (which == 1) ? C1 : C2;

#pragma unroll
    for (int mf = 0; mf < 4; mf++) {
#pragma unroll
        for (int nf = 0; nf < 4; nf++) {
            int col = n0 + warp_n * 32 + nf * 8 + tcol * 2;
            int colr = col & 2047;
            float bb0, bb1;
            if (mode) { bb0 = bp[colr]; bb1 = bp[colr + 1]; }
            else      { bb0 = b0[col];  bb1 = b0[col + 1]; }
            int mrow0 = m0 + warp_m * 64 + mf * 16 + group;
#pragma unroll
            for (int half = 0; half < 2; half++) {
                int mrow = mrow0 + half * 8;
                float v0 = acc[mf][nf][half * 2 + 0] + bb0;
                float v1 = acc[mf][nf][half * 2 + 1] + bb1;
                if (!mode) {
                    *(float2*)(C0 + (size_t)mrow * N + col) = make_float2(v0, v1);
                } else {
                    int b = mrow >> 11;
                    int s = mrow & 2047;
                    int h = colr >> 7;
                    int d = colr & 127;
                    uint2 u = make_uint2(f2tf(v0), f2tf(v1));
                    *(uint2*)(Cw + (((size_t)((b << 4) + h) * SEQ + s) << 7) + d) = u;
                }
            }
        }
    }
}

// =======================================================================
// V transpose: [bh][s][d] -> [bh][d][s]
// =======================================================================
__global__ __launch_bounds__(256)
void transpose_v(const float* __restrict__ in, float* __restrict__ out)
{
    __shared__ float t[32][33];
    const int bh = blockIdx.z;
    const int d0 = blockIdx.x * 32;
    const int s0 = blockIdx.y * 32;
    const float* ip = in  + (size_t)bh * SEQ * HD;
    float*       op = out + (size_t)bh * HD * SEQ;
    const int tx = threadIdx.x & 31;
    const int ty = threadIdx.x >> 5;
#pragma unroll
    for (int j = 0; j < 32; j += 8)
        t[ty + j][tx] = ip[(size_t)(s0 + ty + j) * HD + d0 + tx];
    __syncthreads();
#pragma unroll
    for (int j = 0; j < 32; j += 8)
        op[(size_t)(d0 + ty + j) * SEQ + s0 + tx] = t[tx][ty + j];
}

// =======================================================================
// tf32 flash attention (causal, online softmax).
// Q/K/V arrive as pre-rounded tf32 bits -> raw copy into smem.
// Scale applied to scores in fp32 post-mma. Output rounded to tf32 bits.
// =======================================================================
#define FQ   0
#define FK   8192
#define FV   16384
#define FP   24576
#define FRED 28672
#define FLASH_SMEM ((28672 + 256) * 4)

__global__ __launch_bounds__(256)
void flash_tf32(const float* __restrict__ Q, const float* __restrict__ K,
                const float* __restrict__ Vt, float* __restrict__ Out)
{
    extern __shared__ uint32_t sm[];
    float2* redp = (float2*)(sm + FRED);

    const int tid  = threadIdx.x;
    const int lane = tid & 31;
    const int wid  = tid >> 5;
    const int warp_m = wid & 3;
    const int warp_n = wid >> 2;
    const int qb = (gridDim.x - 1) - blockIdx.x;
    const int bh = blockIdx.y;
    const int g    = lane >> 2;
    const int tcol = lane & 3;
    const float scale = 0.08838834764831845f;

    const float* Qg = Q  + ((size_t)bh * SEQ + qb * 64) * HD;
    const float* Kg = K  + (size_t)bh * SEQ * HD;
    const float* Vg = Vt + (size_t)bh * HD * SEQ;

    const uint32_t sbase = (uint32_t)__cvta_generic_to_shared(sm);
    const int mat = lane >> 3, r = lane & 7;
    const int a_sh = mat >> 1, a_roff = r + ((mat & 1) << 3);
    const int b_sh = mat & 1,  b_roff = r + ((mat >> 1) << 3);

    const uint32_t qa_base = sbase + FQ * 4 + (uint32_t)(warp_m * 16 + a_roff) * 512u;
    uint32_t kb_row[2];
#pragma unroll
    for (int pb = 0; pb < 2; pb++)
        kb_row[pb] = sbase + FK * 4 + (uint32_t)(warp_n * 32 + pb * 16 + b_roff) * 512u;
    const uint32_t pa_base = sbase + FP * 4 + (uint32_t)(warp_m * 16 + a_roff) * 256u;
    uint32_t vb_row[4];
#pragma unroll
    for (int pb = 0; pb < 4; pb++)
        vb_row[pb] = sbase + FV * 4 + (uint32_t)(warp_n * 64 + pb * 16 + b_roff) * 256u;

    // Q tile: raw tf32 bits, swizzled
#pragma unroll
    for (int l = 0; l < 8; l++) {
        int idx = tid + l * 256;
        int row = idx >> 5;
        int seg = idx & 31;
        uint4 u = *(const uint4*)&Qg[row * HD + seg * 4];
        *(uint4*)(sm + FQ + row * 128 + (seg ^ (row & 7)) * 4) = u;
    }

    float o[8][4];
#pragma unroll
    for (int nf = 0; nf < 8; nf++)
#pragma unroll
        for (int c = 0; c < 4; c++) o[nf][c] = 0.f;
    float mrow[2] = {-1e30f, -1e30f};
    float lrow[2] = {0.f, 0.f};

    const int nkb = qb + 1;
    for (int kb = 0; kb < nkb; kb++) {
        __syncthreads();

#pragma unroll
        for (int l = 0; l < 8; l++) {
            int idx = tid + l * 256;
            int row = idx >> 5;
            int seg = idx & 31;
            uint4 u = *(const uint4*)&Kg[(size_t)(kb * 64 + row) * HD + seg * 4];
            *(uint4*)(sm + FK + row * 128 + (seg ^ (row & 7)) * 4) = u;
        }
#pragma unroll
        for (int l = 0; l < 8; l++) {
            int idx = tid + l * 256;
            int d   = idx >> 4;
            int seg = idx & 15;
            uint4 u = *(const uint4*)&Vg[(size_t)d * SEQ + kb * 64 + seg * 4];
            *(uint4*)(sm + FV + d * 64 + (seg ^ (d & 7)) * 4) = u;
        }
        __syncthreads();

        float s[4][4];
#pragma unroll
        for (int nf = 0; nf < 4; nf++)
#pragma unroll
            for (int c = 0; c < 4; c++) s[nf][c] = 0.f;

#pragma unroll
        for (int ks = 0; ks < 16; ks++) {
            uint32_t a0, a1, a2, a3;
            LDSM4(a0, a1, a2, a3, qa_base + (uint32_t)((((ks << 1) + a_sh) ^ r) << 4));
            uint32_t bf[4][2];
#pragma unroll
            for (int pb = 0; pb < 2; pb++) {
                uint32_t t0, t1, t2, t3;
                LDSM4(t0, t1, t2, t3, kb_row[pb] + (uint32_t)((((ks << 1) + b_sh) ^ r) << 4));
                bf[pb * 2 + 0][0] = t0; bf[pb * 2 + 0][1] = t1;
                bf[pb * 2 + 1][0] = t2; bf[pb * 2 + 1][1] = t3;
            }
#pragma unroll
            for (int nf = 0; nf < 4; nf++)
                MMA_TF32(s[nf][0], s[nf][1], s[nf][2], s[nf][3],
                         a0, a1, a2, a3, bf[nf][0], bf[nf][1]);
        }

        // scale + causal mask
#pragma unroll
        for (int nf = 0; nf < 4; nf++)
#pragma unroll
            for (int c = 0; c < 4; c++) s[nf][c] *= scale;
        if (kb == qb) {
#pragma unroll
            for (int nf = 0; nf < 4; nf++)
#pragma unroll
                for (int c = 0; c < 4; c++) {
                    int lr = warp_m * 16 + g + (c >> 1) * 8;
                    int lc = warp_n * 32 + nf * 8 + 2 * tcol + (c & 1);
                    if (lc > lr) s[nf][c] = -1e30f;
                }
        }

        float p[2][8], mxw[2];
#pragma unroll
        for (int h = 0; h < 2; h++) {
            float mx = s[0][h * 2];
#pragma unroll
            for (int nf = 0; nf < 4; nf++) {
                mx = fmaxf(mx, s[nf][h * 2 + 0]);
                mx = fmaxf(mx, s[nf][h * 2 + 1]);
            }
            mx = fmaxf(mx, __shfl_xor_sync(0xffffffffu, mx, 1));
            mx = fmaxf(mx, __shfl_xor_sync(0xffffffffu, mx, 2));
            float sum = 0.f;
#pragma unroll
            for (int nf = 0; nf < 4; nf++) {
                float p0 = __expf(s[nf][h * 2 + 0] - mx);
                float p1 = __expf(s[nf][h * 2 + 1] - mx);
                p[h][nf * 2 + 0] = p0;
                p[h][nf * 2 + 1] = p1;
                sum += p0 + p1;
            }
            sum += __shfl_xor_sync(0xffffffffu, sum, 1);
            sum += __shfl_xor_sync(0xffffffffu, sum, 2);
            mxw[h] = mx;
            if (tcol == 0)
                redp[(warp_m * 16 + g + h * 8) * 2 + warp_n] = make_float2(mx, sum);
        }
        __syncthreads();

#pragma unroll
        for (int h = 0; h < 2; h++) {
            int row = warp_m * 16 + g + h * 8;
            float2 e0 = redp[row * 2 + 0];
            float2 e1 = redp[row * 2 + 1];
            float mnew  = fmaxf(mrow[h], fmaxf(e0.x, e1.x));
            float alpha = __expf(mrow[h] - mnew);
            lrow[h] = lrow[h] * alpha + e0.y * __expf(e0.x - mnew)
                                      + e1.y * __expf(e1.x - mnew);
            mrow[h] = mnew;
            float fac = __expf(mxw[h] - mnew);
#pragma unroll
            for (int nf = 0; nf < 4; nf++) {
                int col = warp_n * 32 + nf * 8 + 2 * tcol;
                uint32_t w = FP + row * 64 + ((col >> 2) ^ (row & 7)) * 4 + (col & 3);
                uint2 u = make_uint2(f2tf(p[h][nf * 2 + 0] * fac),
                                     f2tf(p[h][nf * 2 + 1] * fac));
                *(uint2*)(sm + w) = u;
            }
#pragma unroll
            for (int nfo = 0; nfo < 8; nfo++) {
                o[nfo][h * 2 + 0] *= alpha;
                o[nfo][h * 2 + 1] *= alpha;
            }
        }
        __syncthreads();

#pragma unroll
        for (int ks = 0; ks < 8; ks++) {
            uint32_t a0, a1, a2, a3;
            LDSM4(a0, a1, a2, a3, pa_base + (uint32_t)((((ks << 1) + a_sh) ^ r) << 4));
            uint32_t bf[8][2];
#pragma unroll
            for (int pb = 0; pb < 4; pb++) {
                uint32_t t0, t1, t2, t3;
                LDSM4(t0, t1, t2, t3, vb_row[pb] + (uint32_t)((((ks << 1) + b_sh) ^ r) << 4));
                bf[pb * 2 + 0][0] = t0; bf[pb * 2 + 0][1] = t1;
                bf[pb * 2 + 1][0] = t2; bf[pb * 2 + 1][1] = t3;
            }
#pragma unroll
            for (int nf = 0; nf < 8; nf++)
                MMA_TF32(o[nf][0], o[nf][1], o[nf][2], o[nf][3],
                         a0, a1, a2, a3, bf[nf][0], bf[nf][1]);
        }
    }

    // epilogue: normalize, round to tf32 bits, store merged-heads [B,S,H]
    const int b = bh >> 4;
    const int hh = bh & 15;
#pragma unroll
    for (int h = 0; h < 2; h++) {
        float inv = 1.0f / lrow[h];
        int srow = qb * 64 + warp_m * 16 + g + h * 8;
        float* op = Out + ((size_t)(b * SEQ + srow)) * HIDDEN + hh * HD;
#pragma unroll
        for (int nf = 0; nf < 8; nf++) {
            int d = warp_n * 64 + nf * 8 + 2 * tcol;
            uint2 u = make_uint2(f2tf(o[nf][h * 2 + 0] * inv),
                                 f2tf(o[nf][h * 2 + 1] * inv));
            *(uint2*)(op + d) = u;
        }
    }
}

// =======================================================================
extern "C" void kernel_launch(void* const* d_in, const int* in_sizes, int n_in,
                              void* d_out, int out_size)
{
    const float* x  = (const float*)d_in[0];
    const float* wq = (const float*)d_in[1];
    const float* bq = (const float*)d_in[2];
    const float* wk = (const float*)d_in[3];
    const float* bk = (const float*)d_in[4];
    const float* wv = (const float*)d_in[5];
    const float* bv = (const float*)d_in[6];
    const float* wo = (const float*)d_in[7];
    const float* bo = (const float*)d_in[8];
    float* out = (float*)d_out;

    float *xt, *tw, *two, *q, *k, *v, *vt, *a;
    cudaGetSymbolAddress((void**)&xt,  g_xt);
    cudaGetSymbolAddress((void**)&tw,  g_tw);
    cudaGetSymbolAddress((void**)&two, g_two);
    cudaGetSymbolAddress((void**)&q,   g_q);
    cudaGetSymbolAddress((void**)&k,   g_k);
    cudaGetSymbolAddress((void**)&v,   g_v);
    cudaGetSymbolAddress((void**)&vt,  g_vt);
    cudaGetSymbolAddress((void**)&a,   g_a);

    static int attr_done = 0;
    if (!attr_done) {
        cudaFuncSetAttribute(gemm_cp, cudaFuncAttributeMaxDynamicSharedMemorySize, GEMM_SMEM);
        cudaFuncSetAttribute(flash_tf32, cudaFuncAttributeMaxDynamicSharedMemorySize, FLASH_SMEM);
        attr_done = 1;
    }

    const int WN4 = HIDDEN * HIDDEN / 4;

    // tf32 pre-round: x, packed wq|wk|wv, wo
    cvt_tf32<<<1024, 256>>>(xt, x, MTOT * HIDDEN / 4);
    cvt_tf32<<<1024, 256>>>(tw,               wq, WN4);
    cvt_tf32<<<1024, 256>>>(tw + (size_t)HIDDEN * HIDDEN,     wk, WN4);
    cvt_tf32<<<1024, 256>>>(tw + (size_t)2 * HIDDEN * HIDDEN, wv, WN4);
    cvt_tf32<<<1024, 256>>>(two, wo, WN4);

    // fused QKV projection: N = 6144
    gemm_cp<<<dim3(3 * HIDDEN / 128, MTOT / 128), 256, GEMM_SMEM>>>(
        xt, tw, bq, bk, bv, q, k, v, MTOT, 3 * HIDDEN, HIDDEN, 1);

    transpose_v<<<dim3(HD / 32, SEQ / 32, BATCH * NH), 256>>>(v, vt);

    flash_tf32<<<dim3(SEQ / 64, BATCH * NH), 256, FLASH_SMEM>>>(q, k, vt, a);

    // output projection (full fp32 out)
    gemm_cp<<<dim3(HIDDEN / 128, MTOT / 128), 256, GEMM_SMEM>>>(
        a, two, bo, bo, bo, out, out, out, MTOT, HIDDEN, HIDDEN, 0);
}

// round 7
// speedup vs baseline: 4.6158x; 1.0057x over previous
#include <cuda_runtime.h>
#include <math.h>
#include <stdint.h>

#define HIDDEN 2048
#define NH 16
#define HD 128
#define SEQ 2048
#define BATCH 2
#define MTOT (BATCH*SEQ)   /* 4096 */

// ---------------- scratch (static device memory; no allocation) ----------------
__device__ float g_xt [(size_t)MTOT * HIDDEN];        // x, tf32-rounded
__device__ float g_tw [(size_t)3 * HIDDEN * HIDDEN];  // wq|wk|wv packed, tf32-rounded
__device__ float g_two[(size_t)HIDDEN * HIDDEN];      // wo, tf32-rounded
__device__ float g_q  [(size_t)MTOT * HIDDEN];        // [B,nh,S,hd] (tf32 bits)
__device__ float g_k  [(size_t)MTOT * HIDDEN];        // [B,nh,S,hd] (tf32 bits)
__device__ float g_v  [(size_t)MTOT * HIDDEN];        // [B,nh,S,hd] (tf32 bits)
__device__ float g_vt [(size_t)MTOT * HIDDEN];        // [B,nh,hd,S] (tf32 bits)
__device__ float g_a  [(size_t)MTOT * HIDDEN];        // [B,S,H] attn out (tf32 bits)

__device__ __forceinline__ uint32_t f2tf(float x) {
    uint32_t y;
    asm("cvt.rna.tf32.f32 %0, %1;" : "=r"(y) : "f"(x));
    return y;
}

#define LDSM4(R0,R1,R2,R3,ADDR) \
    asm volatile("ldmatrix.sync.aligned.m8n8.x4.shared.b16 {%0,%1,%2,%3}, [%4];" \
                 : "=r"(R0),"=r"(R1),"=r"(R2),"=r"(R3) : "r"(ADDR))

#define MMA_TF32(C0,C1,C2,C3,A0,A1,A2,A3,B0,B1) \
    asm volatile("mma.sync.aligned.m16n8k8.row.col.f32.tf32.tf32.f32 " \
                 "{%0,%1,%2,%3},{%4,%5,%6,%7},{%8,%9},{%0,%1,%2,%3};" \
                 : "+f"(C0),"+f"(C1),"+f"(C2),"+f"(C3) \
                 : "r"(A0),"r"(A1),"r"(A2),"r"(A3),"r"(B0),"r"(B1))

#define CP_ASYNC16(SA, GA) \
    asm volatile("cp.async.cg.shared.global [%0], [%1], 16;" :: "r"(SA), "l"(GA))
#define CP_COMMIT() asm volatile("cp.async.commit_group;")
#define CP_WAIT1()  asm volatile("cp.async.wait_group 1;")

// =======================================================================
// Single-pass tf32 rounding of x, wq|wk|wv (packed), wo
// =======================================================================
#define NX4 (MTOT * HIDDEN / 4)
#define NW4 (HIDDEN * HIDDEN / 4)
#define NTOT4 (NX4 + 4 * NW4)

__global__ __launch_bounds__(256)
void cvt_all(float* __restrict__ xt, const float* __restrict__ x,
             float* __restrict__ tw, const float* __restrict__ wq,
             const float* __restrict__ wk, const float* __restrict__ wv,
             float* __restrict__ two, const float* __restrict__ wo)
{
    int i = blockIdx.x * blockDim.x + threadIdx.x;
    int stride = gridDim.x * blockDim.x;
    for (; i < NTOT4; i += stride) {
        const float4* sp;
        uint4* dp;
        if (i < NX4) {
            sp = (const float4*)x + i;            dp = (uint4*)xt + i;
        } else {
            int j = i - NX4;
            int w = j / NW4, off = j - w * NW4;
            if      (w == 0) { sp = (const float4*)wq + off; dp = (uint4*)tw + off; }
            else if (w == 1) { sp = (const float4*)wk + off; dp = (uint4*)(tw + (size_t)HIDDEN*HIDDEN) + off; }
            else if (w == 2) { sp = (const float4*)wv + off; dp = (uint4*)(tw + (size_t)2*HIDDEN*HIDDEN) + off; }
            else             { sp = (const float4*)wo + off; dp = (uint4*)two + off; }
        }
        float4 v = *sp;
        *dp = make_uint4(f2tf(v.x), f2tf(v.y), f2tf(v.z), f2tf(v.w));
    }
}

// =======================================================================
// cp.async 3-stage tf32 GEMM (NT) — unchanged from R6.
// =======================================================================
#define STAGES 3
#define STG_U32 8192
#define GEMM_SMEM (STAGES*STG_U32*4)

__global__ __launch_bounds__(256)
void gemm_cp(const float* __restrict__ A, const float* __restrict__ W,
             const float* __restrict__ b0, const float* __restrict__ b1,
             const float* __restrict__ b2,
             float* __restrict__ C0, float* __restrict__ C1, float* __restrict__ C2,
             int M, int N, int K, int mode)
{
    extern __shared__ uint32_t smem_u[];
    const int tid  = threadIdx.x;
    const int lane = tid & 31;
    const int wid  = tid >> 5;
    const int warp_m = wid >> 2;
    const int warp_n = wid & 3;
    const int m0 = blockIdx.y * 128;
    const int n0 = blockIdx.x * 128;

    const int mat = lane >> 3, r = lane & 7;
    const int a_sh = mat >> 1, a_roff = r + ((mat & 1) << 3);
    const int b_sh = mat & 1,  b_roff = r + ((mat >> 1) << 3);

    const int grow = tid >> 3;
    const int gseg = tid & 7;
    const int sseg = gseg ^ (grow & 7);

    const uint32_t sbase = (uint32_t)__cvta_generic_to_shared(smem_u);

    uint32_t sa[4], sb[4];
#pragma unroll
    for (int l = 0; l < 4; l++) {
        sa[l] = sbase + (uint32_t)((grow + 32 * l) * 32 + sseg * 4) * 4u;
        sb[l] = sa[l] + 16384u;
    }

    uint32_t rowbA[4], rowbB[2];
#pragma unroll
    for (int mf = 0; mf < 4; mf++)
        rowbA[mf] = (uint32_t)(warp_m * 64 + mf * 16 + a_roff) * 128u;
#pragma unroll
    for (int pb = 0; pb < 2; pb++)
        rowbB[pb] = (uint32_t)(warp_n * 32 + pb * 16 + b_roff) * 128u + 16384u;

    float acc[4][4][4];
#pragma unroll
    for (int i = 0; i < 4; i++)
#pragma unroll
        for (int j = 0; j < 4; j++)
#pragma unroll
            for (int c = 0; c < 4; c++) acc[i][j][c] = 0.f;

    const int KT = K >> 5;

#pragma unroll
    for (int s = 0; s < STAGES - 1; s++) {
        int k0 = s * 32;
        uint32_t soff = (uint32_t)s * 32768u;
#pragma unroll
        for (int l = 0; l < 4; l++) {
            int row = grow + 32 * l;
            CP_ASYNC16(sa[l] + soff, (const void*)(A + (size_t)(m0 + row) * K + k0 + gseg * 4));
            CP_ASYNC16(sb[l] + soff, (const void*)(W + (size_t)(n0 + row) * K + k0 + gseg * 4));
        }
        CP_COMMIT();
    }

    int stage = 0;
    for (int kt = 0; kt < KT; kt++) {
        CP_WAIT1();
        __syncthreads();

        const uint32_t abase = sbase + (uint32_t)stage * 32768u;
#pragma unroll
        for (int ks = 0; ks < 4; ks++) {
            uint32_t af[4][4];
            uint32_t bf[4][2];
#pragma unroll
            for (int mf = 0; mf < 4; mf++) {
                uint32_t addr = abase + rowbA[mf] + (uint32_t)((((ks << 1) + a_sh) ^ r) << 4);
                LDSM4(af[mf][0], af[mf][1], af[mf][2], af[mf][3], addr);
            }
#pragma unroll
            for (int pb = 0; pb < 2; pb++) {
                uint32_t addr = abase + rowbB[pb] + (uint32_t)((((ks << 1) + b_sh) ^ r) << 4);
                uint32_t t0, t1, t2, t3;
                LDSM4(t0, t1, t2, t3, addr);
                bf[pb * 2 + 0][0] = t0; bf[pb * 2 + 0][1] = t1;
                bf[pb * 2 + 1][0] = t2; bf[pb * 2 + 1][1] = t3;
            }
#pragma unroll
            for (int mf = 0; mf < 4; mf++)
#pragma unroll
                for (int nf = 0; nf < 4; nf++)
                    MMA_TF32(acc[mf][nf][0], acc[mf][nf][1], acc[mf][nf][2], acc[mf][nf][3],
                             af[mf][0], af[mf][1], af[mf][2], af[mf][3],
                             bf[nf][0], bf[nf][1]);
        }

        int kn = kt + STAGES - 1;
        if (kn < KT) {
            int k0 = kn * 32;
            uint32_t soff = (uint32_t)(kn % STAGES) * 32768u;
#pragma unroll
            for (int l = 0; l < 4; l++) {
                int row = grow + 32 * l;
                CP_ASYNC16(sa[l] + soff, (const void*)(A + (size_t)(m0 + row) * K + k0 + gseg * 4));
                CP_ASYNC16(sb[l] + soff, (const void*)(W + (size_t)(n0 + row) * K + k0 + gseg * 4));
            }
        }
        CP_COMMIT();
        stage = (stage + 1 == STAGES) ? 0 : stage + 1;
    }

    const int group = lane >> 2;
    const int tcol  = lane & 3;
    const int which = n0 >> 11;
    const float* bp = (which == 0) ? b0 : (which == 1) ? b1 : b2;
    float* Cw = (which == 0) ? C0 : (which == 1) ? C1 : C2;

#pragma unroll
    for (int mf = 0; mf < 4; mf++) {
#pragma unroll
        for (int nf = 0; nf < 4; nf++) {
            int col = n0 + warp_n * 32 + nf * 8 + tcol * 2;
            int colr = col & 2047;
            float bb0, bb1;
            if (mode) { bb0 = bp[colr]; bb1 = bp[colr + 1]; }
            else      { bb0 = b0[col];  bb1 = b0[col + 1]; }
            int mrow0 = m0 + warp_m * 64 + mf * 16 + group;
#pragma unroll
            for (int half = 0; half < 2; half++) {
                int mrow = mrow0 + half * 8;
                float v0 = acc[mf][nf][half * 2 + 0] + bb0;
                float v1 = acc[mf][nf][half * 2 + 1] + bb1;
                if (!mode) {
                    *(float2*)(C0 + (size_t)mrow * N + col) = make_float2(v0, v1);
                } else {
                    int b = mrow >> 11;
                    int s = mrow & 2047;
                    int h = colr >> 7;
                    int d = colr & 127;
                    uint2 u = make_uint2(f2tf(v0), f2tf(v1));
                    *(uint2*)(Cw + (((size_t)((b << 4) + h) * SEQ + s) << 7) + d) = u;
                }
            }
        }
    }
}

// =======================================================================
// V transpose: [bh][s][d] -> [bh][d][s]
// =======================================================================
__global__ __launch_bounds__(256)
void transpose_v(const float* __restrict__ in, float* __restrict__ out)
{
    __shared__ float t[32][33];
    const int bh = blockIdx.z;
    const int d0 = blockIdx.x * 32;
    const int s0 = blockIdx.y * 32;
    const float* ip = in  + (size_t)bh * SEQ * HD;
    float*       op = out + (size_t)bh * HD * SEQ;
    const int tx = threadIdx.x & 31;
    const int ty = threadIdx.x >> 5;
#pragma unroll
    for (int j = 0; j < 32; j += 8)
        t[ty + j][tx] = ip[(size_t)(s0 + ty + j) * HD + d0 + tx];
    __syncthreads();
#pragma unroll
    for (int j = 0; j < 32; j += 8)
        op[(size_t)(d0 + ty + j) * SEQ + s0 + tx] = t[tx][ty + j];
}

// =======================================================================
// tf32 flash attention, Br=128, Bc=64, 512 threads (16 warps: 8m x 2n).
// Q/K/V are pre-rounded tf32 bits. Scale post-mma. Output tf32 bits.
// Smem u32 layout: Q[128][128] K[64][128] V[128][64] P[128][64] red[256]f2
// =======================================================================
#define FQ   0
#define FK   16384
#define FV   24576
#define FP   32768
#define FRED 40960
#define FLASH_SMEM ((40960 + 512) * 4)   /* 165888 B */

__global__ __launch_bounds__(512)
void flash_tf32(const float* __restrict__ Q, const float* __restrict__ K,
                const float* __restrict__ Vt, float* __restrict__ Out)
{
    extern __shared__ uint32_t sm[];
    float2* redp = (float2*)(sm + FRED);

    const int tid  = threadIdx.x;
    const int lane = tid & 31;
    const int wid  = tid >> 5;
    const int warp_m = wid & 7;          // 8 row groups of 16
    const int warp_n = wid >> 3;         // 2 col groups
    const int qb = (gridDim.x - 1) - blockIdx.x;   // heavy tiles first
    const int bh = blockIdx.y;
    const int g    = lane >> 2;
    const int tcol = lane & 3;
    const float scale = 0.08838834764831845f;

    const float* Qg = Q  + ((size_t)bh * SEQ + qb * 128) * HD;
    const float* Kg = K  + (size_t)bh * SEQ * HD;
    const float* Vg = Vt + (size_t)bh * HD * SEQ;

    const uint32_t sbase = (uint32_t)__cvta_generic_to_shared(sm);
    const int mat = lane >> 3, r = lane & 7;
    const int a_sh = mat >> 1, a_roff = r + ((mat & 1) << 3);
    const int b_sh = mat & 1,  b_roff = r + ((mat >> 1) << 3);

    const uint32_t qa_base = sbase + FQ * 4 + (uint32_t)(warp_m * 16 + a_roff) * 512u;
    uint32_t kb_row[2];
#pragma unroll
    for (int pb = 0; pb < 2; pb++)
        kb_row[pb] = sbase + FK * 4 + (uint32_t)(warp_n * 32 + pb * 16 + b_roff) * 512u;
    const uint32_t pa_base = sbase + FP * 4 + (uint32_t)(warp_m * 16 + a_roff) * 256u;
    uint32_t vb_row[4];
#pragma unroll
    for (int pb = 0; pb < 4; pb++)
        vb_row[pb] = sbase + FV * 4 + (uint32_t)(warp_n * 64 + pb * 16 + b_roff) * 256u;

    // Q tile: 128x128, raw tf32 bits, swizzled (512B rows)
#pragma unroll
    for (int l = 0; l < 8; l++) {
        int idx = tid + l * 512;
        int row = idx >> 5;
        int seg = idx & 31;
        uint4 u = *(const uint4*)&Qg[row * HD + seg * 4];
        *(uint4*)(sm + FQ + row * 128 + (seg ^ (row & 7)) * 4) = u;
    }

    float o[8][4];
#pragma unroll
    for (int nf = 0; nf < 8; nf++)
#pragma unroll
        for (int c = 0; c < 4; c++) o[nf][c] = 0.f;
    float mrow[2] = {-1e30f, -1e30f};
    float lrow[2] = {0.f, 0.f};

    const int nkb = 2 * qb + 2;   // causal: k-tiles of 64 covering [0, (qb+1)*128)
    for (int kb = 0; kb < nkb; kb++) {
        __syncthreads();

        // K tile 64x128 (512B rows)
#pragma unroll
        for (int l = 0; l < 4; l++) {
            int idx = tid + l * 512;
            int row = idx >> 5;
            int seg = idx & 31;
            uint4 u = *(const uint4*)&Kg[(size_t)(kb * 64 + row) * HD + seg * 4];
            *(uint4*)(sm + FK + row * 128 + (seg ^ (row & 7)) * 4) = u;
        }
        // V^T tile 128x64 (256B rows)
#pragma unroll
        for (int l = 0; l < 4; l++) {
            int idx = tid + l * 512;
            int d   = idx >> 4;
            int seg = idx & 15;
            uint4 u = *(const uint4*)&Vg[(size_t)d * SEQ + kb * 64 + seg * 4];
            *(uint4*)(sm + FV + d * 64 + (seg ^ (d & 7)) * 4) = u;
        }
        __syncthreads();

        // ---- scores: S = Q . K^T  (128x64x128) ----
        float s[4][4];
#pragma unroll
        for (int nf = 0; nf < 4; nf++)
#pragma unroll
            for (int c = 0; c < 4; c++) s[nf][c] = 0.f;

#pragma unroll
        for (int ks = 0; ks < 16; ks++) {
            uint32_t a0, a1, a2, a3;
            LDSM4(a0, a1, a2, a3, qa_base + (uint32_t)((((ks << 1) + a_sh) ^ r) << 4));
            uint32_t bf[4][2];
#pragma unroll
            for (int pb = 0; pb < 2; pb++) {
                uint32_t t0, t1, t2, t3;
                LDSM4(t0, t1, t2, t3, kb_row[pb] + (uint32_t)((((ks << 1) + b_sh) ^ r) << 4));
                bf[pb * 2 + 0][0] = t0; bf[pb * 2 + 0][1] = t1;
                bf[pb * 2 + 1][0] = t2; bf[pb * 2 + 1][1] = t3;
            }
#pragma unroll
            for (int nf = 0; nf < 4; nf++)
                MMA_TF32(s[nf][0], s[nf][1], s[nf][2], s[nf][3],
                         a0, a1, a2, a3, bf[nf][0], bf[nf][1]);
        }

        // scale + causal mask (last two k-tiles straddle the diagonal)
#pragma unroll
        for (int nf = 0; nf < 4; nf++)
#pragma unroll
            for (int c = 0; c < 4; c++) s[nf][c] *= scale;
        if (kb >= 2 * qb) {
#pragma unroll
            for (int nf = 0; nf < 4; nf++)
#pragma unroll
                for (int c = 0; c < 4; c++) {
                    int lr = warp_m * 16 + g + (c >> 1) * 8;          // 0..127
                    int lc = warp_n * 32 + nf * 8 + 2 * tcol + (c & 1); // 0..63
                    if (kb * 64 + lc > qb * 128 + lr) s[nf][c] = -1e30f;
                }
        }

        // ---- softmax (one cross-warp exchange over 2 warp_n groups) ----
        float p[2][8], mxw[2];
#pragma unroll
        for (int h = 0; h < 2; h++) {
            float mx = s[0][h * 2];
#pragma unroll
            for (int nf = 0; nf < 4; nf++) {
                mx = fmaxf(mx, s[nf][h * 2 + 0]);
                mx = fmaxf(mx, s[nf][h * 2 + 1]);
            }
            mx = fmaxf(mx, __shfl_xor_sync(0xffffffffu, mx, 1));
            mx = fmaxf(mx, __shfl_xor_sync(0xffffffffu, mx, 2));
            float sum = 0.f;
#pragma unroll
            for (int nf = 0; nf < 4; nf++) {
                float p0 = __expf(s[nf][h * 2 + 0] - mx);
                float p1 = __expf(s[nf][h * 2 + 1] - mx);
                p[h][nf * 2 + 0] = p0;
                p[h][nf * 2 + 1] = p1;
                sum += p0 + p1;
            }
            sum += __shfl_xor_sync(0xffffffffu, sum, 1);
            sum += __shfl_xor_sync(0xffffffffu, sum, 2);
            mxw[h] = mx;
            if (tcol == 0)
                redp[(warp_m * 16 + g + h * 8) * 2 + warp_n] = make_float2(mx, sum);
        }
        __syncthreads();

#pragma unroll
        for (int h = 0; h < 2; h++) {
            int row = warp_m * 16 + g + h * 8;
            float2 e0 = redp[row * 2 + 0];
            float2 e1 = redp[row * 2 + 1];
            float mnew  = fmaxf(mrow[h], fmaxf(e0.x, e1.x));
            float alpha = __expf(mrow[h] - mnew);
            lrow[h] = lrow[h] * alpha + e0.y * __expf(e0.x - mnew)
                                      + e1.y * __expf(e1.x - mnew);
            mrow[h] = mnew;
            float fac = __expf(mxw[h] - mnew);
#pragma unroll
            for (int nf = 0; nf < 4; nf++) {
                int col = warp_n * 32 + nf * 8 + 2 * tcol;
                uint32_t w = FP + row * 64 + ((col >> 2) ^ (row & 7)) * 4 + (col & 3);
                uint2 u = make_uint2(f2tf(p[h][nf * 2 + 0] * fac),
                                     f2tf(p[h][nf * 2 + 1] * fac));
                *(uint2*)(sm + w) = u;
            }
#pragma unroll
            for (int nfo = 0; nfo < 8; nfo++) {
                o[nfo][h * 2 + 0] *= alpha;
                o[nfo][h * 2 + 1] *= alpha;
            }
        }
        __syncthreads();

        // ---- PV: O += P . V  (128x128x64) ----
#pragma unroll
        for (int ks = 0; ks < 8; ks++) {
            uint32_t a0, a1, a2, a3;
            LDSM4(a0, a1, a2, a3, pa_base + (uint32_t)((((ks << 1) + a_sh) ^ r) << 4));
            uint32_t bf[8][2];
#pragma unroll
            for (int pb = 0; pb < 4; pb++) {
                uint32_t t0, t1, t2, t3;
                LDSM4(t0, t1, t2, t3, vb_row[pb] + (uint32_t)((((ks << 1) + b_sh) ^ r) << 4));
                bf[pb * 2 + 0][0] = t0; bf[pb * 2 + 0][1] = t1;
                bf[pb * 2 + 1][0] = t2; bf[pb * 2 + 1][1] = t3;
            }
#pragma unroll
            for (int nf = 0; nf < 8; nf++)
                MMA_TF32(o[nf][0], o[nf][1], o[nf][2], o[nf][3],
                         a0, a1, a2, a3, bf[nf][0], bf[nf][1]);
        }
    }

    // epilogue: normalize, round, store merged-heads [B,S,H]
    const int b = bh >> 4;
    const int hh = bh & 15;
#pragma unroll
    for (int h = 0; h < 2; h++) {
        float inv = 1.0f / lrow[h];
        int srow = qb * 128 + warp_m * 16 + g + h * 8;
        float* op = Out + ((size_t)(b * SEQ + srow)) * HIDDEN + hh * HD;
#pragma unroll
        for (int nf = 0; nf < 8; nf++) {
            int d = warp_n * 64 + nf * 8 + 2 * tcol;
            uint2 u = make_uint2(f2tf(o[nf][h * 2 + 0] * inv),
                                 f2tf(o[nf][h * 2 + 1] * inv));
            *(uint2*)(op + d) = u;
        }
    }
}

// =======================================================================
extern "C" void kernel_launch(void* const* d_in, const int* in_sizes, int n_in,
                              void* d_out, int out_size)
{
    const float* x  = (const float*)d_in[0];
    const float* wq = (const float*)d_in[1];
    const float* bq = (const float*)d_in[2];
    const float* wk = (const float*)d_in[3];
    const float* bk = (const float*)d_in[4];
    const float* wv = (const float*)d_in[5];
    const float* bv = (const float*)d_in[6];
    const float* wo = (const float*)d_in[7];
    const float* bo = (const float*)d_in[8];
    float* out = (float*)d_out;

    float *xt, *tw, *two, *q, *k, *v, *vt, *a;
    cudaGetSymbolAddress((void**)&xt,  g_xt);
    cudaGetSymbolAddress((void**)&tw,  g_tw);
    cudaGetSymbolAddress((void**)&two, g_two);
    cudaGetSymbolAddress((void**)&q,   g_q);
    cudaGetSymbolAddress((void**)&k,   g_k);
    cudaGetSymbolAddress((void**)&v,   g_v);
    cudaGetSymbolAddress((void**)&vt,  g_vt);
    cudaGetSymbolAddress((void**)&a,   g_a);

    static int attr_done = 0;
    if (!attr_done) {
        cudaFuncSetAttribute(gemm_cp, cudaFuncAttributeMaxDynamicSharedMemorySize, GEMM_SMEM);
        cudaFuncSetAttribute(flash_tf32, cudaFuncAttributeMaxDynamicSharedMemorySize, FLASH_SMEM);
        attr_done = 1;
    }

    // tf32 pre-round (single launch)
    cvt_all<<<2048, 256>>>(xt, x, tw, wq, wk, wv, two, wo);

    // fused QKV projection: N = 6144
    gemm_cp<<<dim3(3 * HIDDEN / 128, MTOT / 128), 256, GEMM_SMEM>>>(
        xt, tw, bq, bk, bv, q, k, v, MTOT, 3 * HIDDEN, HIDDEN, 1);

    transpose_v<<<dim3(HD / 32, SEQ / 32, BATCH * NH), 256>>>(v, vt);

    flash_tf32<<<dim3(SEQ / 128, BATCH * NH), 512, FLASH_SMEM>>>(q, k, vt, a);

    // output projection (full fp32 out)
    gemm_cp<<<dim3(HIDDEN / 128, MTOT / 128), 256, GEMM_SMEM>>>(
        a, two, bo, bo, bo, out, out, out, MTOT, HIDDEN, HIDDEN, 0);
}

// round 8
// speedup vs baseline: 4.9668x; 1.0760x over previous
#include <cuda_runtime.h>
#include <math.h>
#include <stdint.h>

#define HIDDEN 2048
#define NH 16
#define HD 128
#define SEQ 2048
#define BATCH 2
#define MTOT (BATCH*SEQ)   /* 4096 */

// ---------------- scratch (static device memory; no allocation) ----------------
__device__ float g_xt [(size_t)MTOT * HIDDEN];        // x, tf32-rounded
__device__ float g_tw [(size_t)3 * HIDDEN * HIDDEN];  // wq|wk|wv packed, tf32-rounded
__device__ float g_two[(size_t)HIDDEN * HIDDEN];      // wo, tf32-rounded
__device__ float g_q  [(size_t)MTOT * HIDDEN];        // [B,nh,S,hd] (tf32 bits)
__device__ float g_k  [(size_t)MTOT * HIDDEN];        // [B,nh,S,hd] (tf32 bits)
__device__ float g_v  [(size_t)MTOT * HIDDEN];        // [B,nh,S,hd] (tf32 bits)
__device__ float g_vt [(size_t)MTOT * HIDDEN];        // [B,nh,hd,S] (tf32 bits)
__device__ float g_a  [(size_t)MTOT * HIDDEN];        // [B,S,H] attn out (tf32 bits)

__device__ __forceinline__ uint32_t f2tf(float x) {
    uint32_t y;
    asm("cvt.rna.tf32.f32 %0, %1;" : "=r"(y) : "f"(x));
    return y;
}

#define LDSM4(R0,R1,R2,R3,ADDR) \
    asm volatile("ldmatrix.sync.aligned.m8n8.x4.shared.b16 {%0,%1,%2,%3}, [%4];" \
                 : "=r"(R0),"=r"(R1),"=r"(R2),"=r"(R3) : "r"(ADDR))

#define MMA_TF32(C0,C1,C2,C3,A0,A1,A2,A3,B0,B1) \
    asm volatile("mma.sync.aligned.m16n8k8.row.col.f32.tf32.tf32.f32 " \
                 "{%0,%1,%2,%3},{%4,%5,%6,%7},{%8,%9},{%0,%1,%2,%3};" \
                 : "+f"(C0),"+f"(C1),"+f"(C2),"+f"(C3) \
                 : "r"(A0),"r"(A1),"r"(A2),"r"(A3),"r"(B0),"r"(B1))

#define CP_ASYNC16(SA, GA) \
    asm volatile("cp.async.cg.shared.global [%0], [%1], 16;" :: "r"(SA), "l"(GA))
#define CP_COMMIT() asm volatile("cp.async.commit_group;")

// =======================================================================
// Single-pass tf32 rounding of x, wq|wk|wv (packed), wo
// =======================================================================
#define NX4 (MTOT * HIDDEN / 4)
#define NW4 (HIDDEN * HIDDEN / 4)
#define NTOT4 (NX4 + 4 * NW4)

__global__ __launch_bounds__(256)
void cvt_all(float* __restrict__ xt, const float* __restrict__ x,
             float* __restrict__ tw, const float* __restrict__ wq,
             const float* __restrict__ wk, const float* __restrict__ wv,
             float* __restrict__ two, const float* __restrict__ wo)
{
    int i = blockIdx.x * blockDim.x + threadIdx.x;
    int stride = gridDim.x * blockDim.x;
    for (; i < NTOT4; i += stride) {
        const float4* sp;
        uint4* dp;
        if (i < NX4) {
            sp = (const float4*)x + i;            dp = (uint4*)xt + i;
        } else {
            int j = i - NX4;
            int w = j / NW4, off = j - w * NW4;
            if      (w == 0) { sp = (const float4*)wq + off; dp = (uint4*)tw + off; }
            else if (w == 1) { sp = (const float4*)wk + off; dp = (uint4*)(tw + (size_t)HIDDEN*HIDDEN) + off; }
            else if (w == 2) { sp = (const float4*)wv + off; dp = (uint4*)(tw + (size_t)2*HIDDEN*HIDDEN) + off; }
            else             { sp = (const float4*)wo + off; dp = (uint4*)two + off; }
        }
        float4 v = *sp;
        *dp = make_uint4(f2tf(v.x), f2tf(v.y), f2tf(v.z), f2tf(v.w));
    }
}

// =======================================================================
// cp.async 3-stage tf32 GEMM (NT) — unchanged (protected win).
// =======================================================================
#define STAGES 3
#define STG_U32 8192
#define GEMM_SMEM (STAGES*STG_U32*4)

__global__ __launch_bounds__(256)
void gemm_cp(const float* __restrict__ A, const float* __restrict__ W,
             const float* __restrict__ b0, const float* __restrict__ b1,
             const float* __restrict__ b2,
             float* __restrict__ C0, float* __restrict__ C1, float* __restrict__ C2,
             int M, int N, int K, int mode)
{
    extern __shared__ uint32_t smem_u[];
    const int tid  = threadIdx.x;
    const int lane = tid & 31;
    const int wid  = tid >> 5;
    const int warp_m = wid >> 2;
    const int warp_n = wid & 3;
    const int m0 = blockIdx.y * 128;
    const int n0 = blockIdx.x * 128;

    const int mat = lane >> 3, r = lane & 7;
    const int a_sh = mat >> 1, a_roff = r + ((mat & 1) << 3);
    const int b_sh = mat & 1,  b_roff = r + ((mat >> 1) << 3);

    const int grow = tid >> 3;
    const int gseg = tid & 7;
    const int sseg = gseg ^ (grow & 7);

    const uint32_t sbase = (uint32_t)__cvta_generic_to_shared(smem_u);

    uint32_t sa[4], sb[4];
#pragma unroll
    for (int l = 0; l < 4; l++) {
        sa[l] = sbase + (uint32_t)((grow + 32 * l) * 32 + sseg * 4) * 4u;
        sb[l] = sa[l] + 16384u;
    }

    uint32_t rowbA[4], rowbB[2];
#pragma unroll
    for (int mf = 0; mf < 4; mf++)
        rowbA[mf] = (uint32_t)(warp_m * 64 + mf * 16 + a_roff) * 128u;
#pragma unroll
    for (int pb = 0; pb < 2; pb++)
        rowbB[pb] = (uint32_t)(warp_n * 32 + pb * 16 + b_roff) * 128u + 16384u;

    float acc[4][4][4];
#pragma unroll
    for (int i = 0; i < 4; i++)
#pragma unroll
        for (int j = 0; j < 4; j++)
#pragma unroll
            for (int c = 0; c < 4; c++) acc[i][j][c] = 0.f;

    const int KT = K >> 5;

#pragma unroll
    for (int s = 0; s < STAGES - 1; s++) {
        int k0 = s * 32;
        uint32_t soff = (uint32_t)s * 32768u;
#pragma unroll
        for (int l = 0; l < 4; l++) {
            int row = grow + 32 * l;
            CP_ASYNC16(sa[l] + soff, (const void*)(A + (size_t)(m0 + row) * K + k0 + gseg * 4));
            CP_ASYNC16(sb[l] + soff, (const void*)(W + (size_t)(n0 + row) * K + k0 + gseg * 4));
        }
        CP_COMMIT();
    }

    int stage = 0;
    for (int kt = 0; kt < KT; kt++) {
        asm volatile("cp.async.wait_group 1;");
        __syncthreads();

        const uint32_t abase = sbase + (uint32_t)stage * 32768u;
#pragma unroll
        for (int ks = 0; ks < 4; ks++) {
            uint32_t af[4][4];
            uint32_t bf[4][2];
#pragma unroll
            for (int mf = 0; mf < 4; mf++) {
                uint32_t addr = abase + rowbA[mf] + (uint32_t)((((ks << 1) + a_sh) ^ r) << 4);
                LDSM4(af[mf][0], af[mf][1], af[mf][2], af[mf][3], addr);
            }
#pragma unroll
            for (int pb = 0; pb < 2; pb++) {
                uint32_t addr = abase + rowbB[pb] + (uint32_t)((((ks << 1) + b_sh) ^ r) << 4);
                uint32_t t0, t1, t2, t3;
                LDSM4(t0, t1, t2, t3, addr);
                bf[pb * 2 + 0][0] = t0; bf[pb * 2 + 0][1] = t1;
                bf[pb * 2 + 1][0] = t2; bf[pb * 2 + 1][1] = t3;
            }
#pragma unroll
            for (int mf = 0; mf < 4; mf++)
#pragma unroll
                for (int nf = 0; nf < 4; nf++)
                    MMA_TF32(acc[mf][nf][0], acc[mf][nf][1], acc[mf][nf][2], acc[mf][nf][3],
                             af[mf][0], af[mf][1], af[mf][2], af[mf][3],
                             bf[nf][0], bf[nf][1]);
        }

        int kn = kt + STAGES - 1;
        if (kn < KT) {
            int k0 = kn * 32;
            uint32_t soff = (uint32_t)(kn % STAGES) * 32768u;
#pragma unroll
            for (int l = 0; l < 4; l++) {
                int row = grow + 32 * l;
                CP_ASYNC16(sa[l] + soff, (const void*)(A + (size_t)(m0 + row) * K + k0 + gseg * 4));
                CP_ASYNC16(sb[l] + soff, (const void*)(W + (size_t)(n0 + row) * K + k0 + gseg * 4));
            }
        }
        CP_COMMIT();
        stage = (stage + 1 == STAGES) ? 0 : stage + 1;
    }

    const int group = lane >> 2;
    const int tcol  = lane & 3;
    const int which = n0 >> 11;
    const float* bp = (which == 0) ? b0 : (which == 1) ? b1 : b2;
    float* Cw = (which == 0) ? C0 : (which == 1) ? C1 : C2;

#pragma unroll
    for (int mf = 0; mf < 4; mf++) {
#pragma unroll
        for (int nf = 0; nf < 4; nf++) {
            int col = n0 + warp_n * 32 + nf * 8 + tcol * 2;
            int colr = col & 2047;
            float bb0, bb1;
            if (mode) { bb0 = bp[colr]; bb1 = bp[colr + 1]; }
            else      { bb0 = b0[col];  bb1 = b0[col + 1]; }
            int mrow0 = m0 + warp_m * 64 + mf * 16 + group;
#pragma unroll
            for (int half = 0; half < 2; half++) {
                int mrow = mrow0 + half * 8;
                float v0 = acc[mf][nf][half * 2 + 0] + bb0;
                float v1 = acc[mf][nf][half * 2 + 1] + bb1;
                if (!mode) {
                    *(float2*)(C0 + (size_t)mrow * N + col) = make_float2(v0, v1);
                } else {
                    int b = mrow >> 11;
                    int s = mrow & 2047;
                    int h = colr >> 7;
                    int d = colr & 127;
                    uint2 u = make_uint2(f2tf(v0), f2tf(v1));
                    *(uint2*)(Cw + (((size_t)((b << 4) + h) * SEQ + s) << 7) + d) = u;
                }
            }
        }
    }
}

// =======================================================================
// V transpose: [bh][s][d] -> [bh][d][s]
// =======================================================================
__global__ __launch_bounds__(256)
void transpose_v(const float* __restrict__ in, float* __restrict__ out)
{
    __shared__ float t[32][33];
    const int bh = blockIdx.z;
    const int d0 = blockIdx.x * 32;
    const int s0 = blockIdx.y * 32;
    const float* ip = in  + (size_t)bh * SEQ * HD;
    float*       op = out + (size_t)bh * HD * SEQ;
    const int tx = threadIdx.x & 31;
    const int ty = threadIdx.x >> 5;
#pragma unroll
    for (int j = 0; j < 32; j += 8)
        t[ty + j][tx] = ip[(size_t)(s0 + ty + j) * HD + d0 + tx];
    __syncthreads();
#pragma unroll
    for (int j = 0; j < 32; j += 8)
        op[(size_t)(d0 + ty + j) * SEQ + s0 + tx] = t[tx][ty + j];
}

// =======================================================================
// tf32 flash attention, Br=128, Bc=64, 512 threads, cp.async pipelined:
//   K double-buffered (prefetch next tile), V early-issued single buffer.
// Smem u32: Q[16384] K0[8192] K1[8192] V[8192] P[8192] red[512]
// =======================================================================
#define FQ   0
#define FK0  16384
#define FV   32768
#define FP   40960
#define FRED 49152
#define FLASH_SMEM ((49152 + 512) * 4)   /* 198656 B */

__global__ __launch_bounds__(512)
void flash_tf32(const float* __restrict__ Q, const float* __restrict__ K,
                const float* __restrict__ Vt, float* __restrict__ Out)
{
    extern __shared__ uint32_t sm[];
    float2* redp = (float2*)(sm + FRED);

    const int tid  = threadIdx.x;
    const int lane = tid & 31;
    const int wid  = tid >> 5;
    const int warp_m = wid & 7;          // 8 row groups of 16
    const int warp_n = wid >> 3;         // 2 col groups
    const int qb = (gridDim.x - 1) - blockIdx.x;   // heavy tiles first
    const int bh = blockIdx.y;
    const int g    = lane >> 2;
    const int tcol = lane & 3;
    const float scale = 0.08838834764831845f;

    const float* Qg = Q  + ((size_t)bh * SEQ + qb * 128) * HD;
    const float* Kg = K  + (size_t)bh * SEQ * HD;
    const float* Vg = Vt + (size_t)bh * HD * SEQ;

    const uint32_t sbase = (uint32_t)__cvta_generic_to_shared(sm);
    const int mat = lane >> 3, r = lane & 7;
    const int a_sh = mat >> 1, a_roff = r + ((mat & 1) << 3);
    const int b_sh = mat & 1,  b_roff = r + ((mat >> 1) << 3);

    // ldmatrix bases
    const uint32_t qa_base = sbase + (uint32_t)(warp_m * 16 + a_roff) * 512u;
    uint32_t kb_row[2];   // relative to K0; add kcur byte offset per iter
#pragma unroll
    for (int pb = 0; pb < 2; pb++)
        kb_row[pb] = sbase + FK0 * 4 + (uint32_t)(warp_n * 32 + pb * 16 + b_roff) * 512u;
    const uint32_t pa_base = sbase + FP * 4 + (uint32_t)(warp_m * 16 + a_roff) * 256u;
    uint32_t vb_row[4];
#pragma unroll
    for (int pb = 0; pb < 4; pb++)
        vb_row[pb] = sbase + FV * 4 + (uint32_t)(warp_n * 64 + pb * 16 + b_roff) * 256u;

    // cp.async per-thread addressing (512 threads)
    const int krow = tid >> 5;          // +16*l -> 64 rows
    const int kseg = tid & 31;
    const int ksw  = kseg ^ (krow & 7); // row&7 invariant across l (16l % 8 == 0)
    uint32_t kdst[4];
#pragma unroll
    for (int l = 0; l < 4; l++)
        kdst[l] = sbase + (uint32_t)(FK0 + (krow + 16 * l) * 128 + ksw * 4) * 4u;

    const int vrow = tid >> 4;          // +32*l -> 128 rows (d)
    const int vseg = tid & 15;
    const int vsw  = vseg ^ (vrow & 7); // d&7 invariant across l (32l % 8 == 0)
    uint32_t vdst[4];
#pragma unroll
    for (int l = 0; l < 4; l++)
        vdst[l] = sbase + (uint32_t)(FV + (vrow + 32 * l) * 64 + vsw * 4) * 4u;

    // ---- Q tile 128x128: raw tf32 bits, swizzled ----
#pragma unroll
    for (int l = 0; l < 8; l++) {
        int idx = tid + l * 512;
        int row = idx >> 5;
        int seg = idx & 31;
        uint4 u = *(const uint4*)&Qg[row * HD + seg * 4];
        *(uint4*)(sm + row * 128 + (seg ^ (row & 7)) * 4) = u;
    }

    // ---- prologue: prefetch K[0] ----
#pragma unroll
    for (int l = 0; l < 4; l++)
        CP_ASYNC16(kdst[l], (const void*)(Kg + (size_t)(krow + 16 * l) * HD + kseg * 4));
    CP_COMMIT();

    float o[8][4];
#pragma unroll
    for (int nf = 0; nf < 8; nf++)
#pragma unroll
        for (int c = 0; c < 4; c++) o[nf][c] = 0.f;
    float mrow[2] = {-1e30f, -1e30f};
    float lrow[2] = {0.f, 0.f};

    const int nkb = 2 * qb + 2;   // k-tiles of 64 covering [0, (qb+1)*128)
    for (int kb = 0; kb < nkb; kb++) {
        const uint32_t kcur = (kb & 1) ? 32768u : 0u;   // byte offset of live K buffer
        __syncthreads();   // V/P free from prev PV; Q visible (iter 0)

        // issue V[kb] (needed only at PV)
#pragma unroll
        for (int l = 0; l < 4; l++)
            CP_ASYNC16(vdst[l], (const void*)(Vg + (size_t)(vrow + 32 * l) * SEQ + kb * 64 + vseg * 4));
        CP_COMMIT();
        // issue K[kb+1] into alternate buffer (needed next iter)
        if (kb + 1 < nkb) {
            uint32_t koff = (kb & 1) ? 0u : 32768u;
#pragma unroll
            for (int l = 0; l < 4; l++)
                CP_ASYNC16(kdst[l] + koff,
                           (const void*)(Kg + (size_t)((kb + 1) * 64 + krow + 16 * l) * HD + kseg * 4));
        }
        CP_COMMIT();

        asm volatile("cp.async.wait_group 2;");   // K[kb] resident
        __syncthreads();

        // ---- scores: S = Q . K^T  (128x64x128) ----
        float s[4][4];
#pragma unroll
        for (int nf = 0; nf < 4; nf++)
#pragma unroll
            for (int c = 0; c < 4; c++) s[nf][c] = 0.f;

#pragma unroll
        for (int ks = 0; ks < 16; ks++) {
            uint32_t a0, a1, a2, a3;
            LDSM4(a0, a1, a2, a3, qa_base + (uint32_t)((((ks << 1) + a_sh) ^ r) << 4));
            uint32_t bf[4][2];
#pragma unroll
            for (int pb = 0; pb < 2; pb++) {
                uint32_t t0, t1, t2, t3;
                LDSM4(t0, t1, t2, t3, kb_row[pb] + kcur + (uint32_t)((((ks << 1) + b_sh) ^ r) << 4));
                bf[pb * 2 + 0][0] = t0; bf[pb * 2 + 0][1] = t1;
                bf[pb * 2 + 1][0] = t2; bf[pb * 2 + 1][1] = t3;
            }
#pragma unroll
            for (int nf = 0; nf < 4; nf++)
                MMA_TF32(s[nf][0], s[nf][1], s[nf][2], s[nf][3],
                         a0, a1, a2, a3, bf[nf][0], bf[nf][1]);
        }

        // scale + causal mask (tiles straddling the diagonal)
#pragma unroll
        for (int nf = 0; nf < 4; nf++)
#pragma unroll
            for (int c = 0; c < 4; c++) s[nf][c] *= scale;
        if (kb >= 2 * qb) {
#pragma unroll
            for (int nf = 0; nf < 4; nf++)
#pragma unroll
                for (int c = 0; c < 4; c++) {
                    int lr = warp_m * 16 + g + (c >> 1) * 8;
                    int lc = warp_n * 32 + nf * 8 + 2 * tcol + (c & 1);
                    if (kb * 64 + lc > qb * 128 + lr) s[nf][c] = -1e30f;
                }
        }

        // ---- softmax ----
        float p[2][8], mxw[2];
#pragma unroll
        for (int h = 0; h < 2; h++) {
            float mx = s[0][h * 2];
#pragma unroll
            for (int nf = 0; nf < 4; nf++) {
                mx = fmaxf(mx, s[nf][h * 2 + 0]);
                mx = fmaxf(mx, s[nf][h * 2 + 1]);
            }
            mx = fmaxf(mx, __shfl_xor_sync(0xffffffffu, mx, 1));
            mx = fmaxf(mx, __shfl_xor_sync(0xffffffffu, mx, 2));
            float sum = 0.f;
#pragma unroll
            for (int nf = 0; nf < 4; nf++) {
                float p0 = __expf(s[nf][h * 2 + 0] - mx);
                float p1 = __expf(s[nf][h * 2 + 1] - mx);
                p[h][nf * 2 + 0] = p0;
                p[h][nf * 2 + 1] = p1;
                sum += p0 + p1;
            }
            sum += __shfl_xor_sync(0xffffffffu, sum, 1);
            sum += __shfl_xor_sync(0xffffffffu, sum, 2);
            mxw[h] = mx;
            if (tcol == 0)
                redp[(warp_m * 16 + g + h * 8) * 2 + warp_n] = make_float2(mx, sum);
        }
        __syncthreads();

#pragma unroll
        for (int h = 0; h < 2; h++) {
            int row = warp_m * 16 + g + h * 8;
            float2 e0 = redp[row * 2 + 0];
            float2 e1 = redp[row * 2 + 1];
            float mnew  = fmaxf(mrow[h], fmaxf(e0.x, e1.x));
            float alpha = __expf(mrow[h] - mnew);
            lrow[h] = lrow[h] * alpha + e0.y * __expf(e0.x - mnew)
                                      + e1.y * __expf(e1.x - mnew);
            mrow[h] = mnew;
            float fac = __expf(mxw[h] - mnew);
#pragma unroll
            for (int nf = 0; nf < 4; nf++) {
                int col = warp_n * 32 + nf * 8 + 2 * tcol;
                uint32_t w = FP + row * 64 + ((col >> 2) ^ (row & 7)) * 4 + (col & 3);
                uint2 u = make_uint2(f2tf(p[h][nf * 2 + 0] * fac),
                                     f2tf(p[h][nf * 2 + 1] * fac));
                *(uint2*)(sm + w) = u;
            }
#pragma unroll
            for (int nfo = 0; nfo < 8; nfo++) {
                o[nfo][h * 2 + 0] *= alpha;
                o[nfo][h * 2 + 1] *= alpha;
            }
        }

        asm volatile("cp.async.wait_group 1;");   // V[kb] resident (K[kb+1] may fly)
        __syncthreads();   // P + V visible to all warps

        // ---- PV: O += P . V  (128x128x64) ----
#pragma unroll
        for (int ks = 0; ks < 8; ks++) {
            uint32_t a0, a1, a2, a3;
            LDSM4(a0, a1, a2, a3, pa_base + (uint32_t)((((ks << 1) + a_sh) ^ r) << 4));
            uint32_t bf[8][2];
#pragma unroll
            for (int pb = 0; pb < 4; pb++) {
                uint32_t t0, t1, t2, t3;
                LDSM4(t0, t1, t2, t3, vb_row[pb] + (uint32_t)((((ks << 1) + b_sh) ^ r) << 4));
                bf[pb * 2 + 0][0] = t0; bf[pb * 2 + 0][1] = t1;
                bf[pb * 2 + 1][0] = t2; bf[pb * 2 + 1][1] = t3;
            }
#pragma unroll
            for (int nf = 0; nf < 8; nf++)
                MMA_TF32(o[nf][0], o[nf][1], o[nf][2], o[nf][3],
                         a0, a1, a2, a3, bf[nf][0], bf[nf][1]);
        }
    }

    // ---- epilogue: normalize, round, store merged-heads [B,S,H] ----
    const int b = bh >> 4;
    const int hh = bh & 15;
#pragma unroll
    for (int h = 0; h < 2; h++) {
        float inv = 1.0f / lrow[h];
        int srow = qb * 128 + warp_m * 16 + g + h * 8;
        float* op = Out + ((size_t)(b * SEQ + srow)) * HIDDEN + hh * HD;
#pragma unroll
        for (int nf = 0; nf < 8; nf++) {
            int d = warp_n * 64 + nf * 8 + 2 * tcol;
            uint2 u = make_uint2(f2tf(o[nf][h * 2 + 0] * inv),
                                 f2tf(o[nf][h * 2 + 1] * inv));
            *(uint2*)(op + d) = u;
        }
    }
}

// =======================================================================
extern "C" void kernel_launch(void* const* d_in, const int* in_sizes, int n_in,
                              void* d_out, int out_size)
{
    const float* x  = (const float*)d_in[0];
    const float* wq = (const float*)d_in[1];
    const float* bq = (const float*)d_in[2];
    const float* wk = (const float*)d_in[3];
    const float* bk = (const float*)d_in[4];
    const float* wv = (const float*)d_in[5];
    const float* bv = (const float*)d_in[6];
    const float* wo = (const float*)d_in[7];
    const float* bo = (const float*)d_in[8];
    float* out = (float*)d_out;

    float *xt, *tw, *two, *q, *k, *v, *vt, *a;
    cudaGetSymbolAddress((void**)&xt,  g_xt);
    cudaGetSymbolAddress((void**)&tw,  g_tw);
    cudaGetSymbolAddress((void**)&two, g_two);
    cudaGetSymbolAddress((void**)&q,   g_q);
    cudaGetSymbolAddress((void**)&k,   g_k);
    cudaGetSymbolAddress((void**)&v,   g_v);
    cudaGetSymbolAddress((void**)&vt,  g_vt);
    cudaGetSymbolAddress((void**)&a,   g_a);

    static int attr_done = 0;
    if (!attr_done) {
        cudaFuncSetAttribute(gemm_cp, cudaFuncAttributeMaxDynamicSharedMemorySize, GEMM_SMEM);
        cudaFuncSetAttribute(flash_tf32, cudaFuncAttributeMaxDynamicSharedMemorySize, FLASH_SMEM);
        attr_done = 1;
    }

    // tf32 pre-round (single launch)
    cvt_all<<<2048, 256>>>(xt, x, tw, wq, wk, wv, two, wo);

    // fused QKV projection: N = 6144
    gemm_cp<<<dim3(3 * HIDDEN / 128, MTOT / 128), 256, GEMM_SMEM>>>(
        xt, tw, bq, bk, bv, q, k, v, MTOT, 3 * HIDDEN, HIDDEN, 1);

    transpose_v<<<dim3(HD / 32, SEQ / 32, BATCH * NH), 256>>>(v, vt);

    flash_tf32<<<dim3(SEQ / 128, BATCH * NH), 512, FLASH_SMEM>>>(q, k, vt, a);

    // output projection (full fp32 out)
    gemm_cp<<<dim3(HIDDEN / 128, MTOT / 128), 256, GEMM_SMEM>>>(
        a, two, bo, bo, bo, out, out, out, MTOT, HIDDEN, HIDDEN, 0);
}